// round 7
// baseline (speedup 1.0000x reference)
#include <cuda_runtime.h>

// ---------------------------------------------------------------------------
// SAGEConv (cugraph, mean agg, concat root):
//   detect -> hist -> single-block scan -> fill -> FUSED agg+GEMM (+cnt zero)
// ---------------------------------------------------------------------------

#define N_MAX 100000
#define E_MAX 1600000
#define F 64
#define KDIM 128
#define APAD 68   // tile row stride (multiple of 4 floats -> 16B-aligned rows)

// Scratch (__device__ globals; zero-initialized at load, g_cnt kept zeroed
// across calls by fused_kernel's epilogue)
__device__ int g_cnt[N_MAX];
__device__ int g_rowptr[N_MAX];
__device__ int g_cursor[N_MAX];
__device__ int g_ebuf[E_MAX];
__device__ int g_is64;

// --------------------------------------------------------------------------
__device__ __forceinline__ int edge_src(const int* ei, int is64, int E, int e, int N) {
    int v = is64 ? ei[2 * e] : ei[e];
    return min(max(v, 0), N - 1);
}
__device__ __forceinline__ int edge_dst(const int* ei, int is64, int E, int e, int N) {
    int v = is64 ? ei[2 * E + 2 * e] : ei[E + e];
    return min(max(v, 0), N - 1);
}

// packed f32x2 helpers (Blackwell sm_10x)
__device__ __forceinline__ unsigned long long ffma2(unsigned long long a,
                                                    unsigned long long b,
                                                    unsigned long long c) {
    unsigned long long d;
    asm("fma.rn.f32x2 %0, %1, %2, %3;" : "=l"(d) : "l"(a), "l"(b), "l"(c));
    return d;
}
__device__ __forceinline__ unsigned long long dup2(float w) {
    unsigned long long r;
    asm("mov.b64 %0, {%1, %1};" : "=l"(r) : "f"(w));
    return r;
}
__device__ __forceinline__ float2 unpack2(unsigned long long v) {
    float2 r;
    asm("mov.b64 {%0, %1}, %2;" : "=f"(r.x), "=f"(r.y) : "l"(v));
    return r;
}

// --------------------------------------------------------------------------
// edge dtype detect: int64 little-endian values < 2^31 -> all hi words zero
__global__ void detect_kernel(const int* __restrict__ ei, int E) {
    int ok = 1;
    int n = min(E, 2048);
    for (int j = threadIdx.x; j < n; j += blockDim.x)
        if (ei[2 * j + 1] != 0) ok = 0;
    int all_ok = __syncthreads_and(ok);
    if (threadIdx.x == 0) g_is64 = all_ok ? 1 : 0;
}

// histogram of destinations (g_cnt must be zero on entry — maintained by
// fused_kernel's epilogue + initial BSS zero)
__global__ void hist_kernel(const int* __restrict__ ei, int E, int N) {
    int e = blockIdx.x * blockDim.x + threadIdx.x;
    if (e < E) {
        int is64 = g_is64;
        atomicAdd(&g_cnt[edge_dst(ei, is64, E, e, N)], 1);
    }
}

// Single-block exclusive scan of g_cnt -> g_rowptr & g_cursor.
// 1024 threads, ~98 contiguous elems per thread, 2 passes.
__global__ __launch_bounds__(1024)
void scan_kernel(int N) {
    const int T = 1024;
    int tid = threadIdx.x, lane = tid & 31, wid = tid >> 5;
    int chunk = (N + T - 1) / T;
    int base = tid * chunk;
    int end  = min(base + chunk, N);

    // pass 1: local sum (independent loads, high MLP)
    int local = 0;
    for (int i = base; i < end; i++) local += g_cnt[i];

    // block exclusive scan of 1024 locals via warp shuffles
    int s = local;
    #pragma unroll
    for (int o = 1; o < 32; o <<= 1) {
        int t = __shfl_up_sync(0xffffffffu, s, o);
        if (lane >= o) s += t;
    }
    __shared__ int wsum[32];
    if (lane == 31) wsum[wid] = s;
    __syncthreads();
    if (tid < 32) {
        int t = wsum[tid];
        int ss = t;
        #pragma unroll
        for (int o = 1; o < 32; o <<= 1) {
            int u = __shfl_up_sync(0xffffffffu, ss, o);
            if (tid >= o) ss += u;
        }
        wsum[tid] = ss - t;   // exclusive warp offsets
    }
    __syncthreads();
    int run = wsum[wid] + s - local;   // exclusive offset for this thread

    // pass 2: local exclusive rescan (cnt re-reads hit L1/L2)
    for (int i = base; i < end; i++) {
        g_rowptr[i] = run;
        g_cursor[i] = run;
        run += g_cnt[i];
    }
}

// bucket fill: ebuf[dst-grouped] = src
__global__ void fill_kernel(const int* __restrict__ ei, int E, int N) {
    int e = blockIdx.x * blockDim.x + threadIdx.x;
    if (e < E) {
        int is64 = g_is64;
        int d = edge_dst(ei, is64, E, e, N);
        int pos = atomicAdd(&g_cursor[d], 1);
        if (pos >= 0 && pos < E_MAX)
            g_ebuf[pos] = edge_src(ei, is64, E, e, N);
    }
}

// --------------------------------------------------------------------------
// Inner 64x64x64 MMA step: packed f32x2, node-pairs in 64-bit accumulators.
__device__ __forceinline__ void mma_tile(const float (*As)[APAD], const float (*Ws)[APAD],
                                         unsigned long long acc[2][4], int tx, int ty) {
    #pragma unroll 8
    for (int k = 0; k < 64; k++) {
        float4 a4 = *(const float4*)&As[k][ty * 4];
        float4 w4 = *(const float4*)&Ws[k][tx * 4];
        unsigned long long a01, a23;
        asm("mov.b64 %0, {%1, %2};" : "=l"(a01) : "f"(a4.x), "f"(a4.y));
        asm("mov.b64 %0, {%1, %2};" : "=l"(a23) : "f"(a4.z), "f"(a4.w));
        float wj[4] = {w4.x, w4.y, w4.z, w4.w};
        #pragma unroll
        for (int j = 0; j < 4; j++) {
            unsigned long long wd = dup2(wj[j]);
            acc[0][j] = ffma2(a01, wd, acc[0][j]);
            acc[1][j] = ffma2(a23, wd, acc[1][j]);
        }
    }
}

// Fused: gather-aggregate (mean) -> concat GEMM + bias; zeroes own g_cnt slice.
__global__ __launch_bounds__(256)
void fused_kernel(const float2* __restrict__ x2,
                  const float*  __restrict__ W,      // [64][128]
                  const float*  __restrict__ bias,   // [64]
                  float* __restrict__ out, int N) {
    __shared__ float As[64][APAD];   // [k][node]
    __shared__ float Ws[64][APAD];   // [k][o]

    int tid  = threadIdx.x;
    int lane = tid & 31, warp = tid >> 5;
    int tx = tid & 15, ty = tid >> 4;
    int n0 = blockIdx.x * 64;

    unsigned long long acc[2][4];
    #pragma unroll
    for (int p = 0; p < 2; p++)
        #pragma unroll
        for (int j = 0; j < 4; j++) acc[p][j] = 0ULL;

    // ---- stage Ws (kt=0) ----
    for (int i = tid; i < 64 * 64; i += 256) {
        int o = i >> 6, k = i & 63;
        Ws[k][o] = W[o * KDIM + k];
    }

    // ---- aggregate: 8 nodes per warp, lane owns feature pair (2l, 2l+1) ----
    for (int t = 0; t < 8; t++) {
        int nloc = warp * 8 + t;
        int node = n0 + nloc;
        float2 a = make_float2(0.f, 0.f);
        float inv = 1.f;
        if (node < N) {
            int start = g_rowptr[node];
            int deg   = g_cnt[node];
            for (int base = 0; base < deg; base += 32) {
                int rem = deg - base;
                int cnt = rem < 32 ? rem : 32;
                int myidx = (lane < cnt) ? g_ebuf[start + base + lane] : 0;
                #pragma unroll 4
                for (int j = 0; j < cnt; j++) {
                    int s = __shfl_sync(0xffffffffu, myidx, j);
                    float2 v = __ldg(x2 + (size_t)s * 32 + lane);
                    a.x += v.x; a.y += v.y;
                }
            }
            inv = 1.0f / (float)(deg > 1 ? deg : 1);
        }
        As[2 * lane][nloc]     = a.x * inv;
        As[2 * lane + 1][nloc] = a.y * inv;
    }
    __syncthreads();

    // ---- MMA kt=0 (agg half) ----
    mma_tile(As, Ws, acc, tx, ty);
    __syncthreads();

    // ---- stage Ws (kt=1) + x tile (transposed) ----
    for (int i = tid; i < 64 * 64; i += 256) {
        int o = i >> 6, k = i & 63;
        Ws[k][o] = W[o * KDIM + 64 + k];
    }
    for (int t = 0; t < 8; t++) {
        int nloc = warp * 8 + t;
        int node = n0 + nloc;
        float2 v = make_float2(0.f, 0.f);
        if (node < N) v = __ldg(x2 + (size_t)node * 32 + lane);
        As[2 * lane][nloc]     = v.x;
        As[2 * lane + 1][nloc] = v.y;
    }
    __syncthreads();

    // ---- MMA kt=1 (self half) ----
    mma_tile(As, Ws, acc, tx, ty);

    // ---- epilogue: +bias, float4 stores ----
    float4 bv = *(const float4*)(bias + tx * 4);
    #pragma unroll
    for (int p = 0; p < 2; p++) {
        float2 c0 = unpack2(acc[p][0]);
        float2 c1 = unpack2(acc[p][1]);
        float2 c2 = unpack2(acc[p][2]);
        float2 c3 = unpack2(acc[p][3]);
        int n = n0 + ty * 4 + 2 * p;
        if (n < N) {
            float4 o4 = make_float4(c0.x + bv.x, c1.x + bv.y, c2.x + bv.z, c3.x + bv.w);
            ((float4*)out)[(size_t)n * 16 + tx] = o4;
        }
        if (n + 1 < N) {
            float4 o4 = make_float4(c0.y + bv.x, c1.y + bv.y, c2.y + bv.z, c3.y + bv.w);
            ((float4*)out)[(size_t)(n + 1) * 16 + tx] = o4;
        }
    }

    // ---- zero own g_cnt slice for the next call (replaces prep kernel) ----
    if (tid < 64) {
        int n = n0 + tid;
        if (n < N) g_cnt[n] = 0;
    }
}

// --------------------------------------------------------------------------
extern "C" void kernel_launch(void* const* d_in, const int* in_sizes, int n_in,
                              void* d_out, int out_size) {
    const float* x  = nullptr;
    const int*   ei = nullptr;
    const float* W  = nullptr;
    const float* b  = nullptr;
    int xsz = 0, esz = 0;

    for (int i = 0; i < n_in; i++) {
        int sz = in_sizes[i];
        if (sz == 64) b = (const float*)d_in[i];
        else if (sz == 8192) W = (const float*)d_in[i];
        else if (sz <= 2) { /* num_nodes scalar */ }
        else {
            if (sz > xsz) {
                if (x) { ei = (const int*)x; esz = xsz; }
                x = (const float*)d_in[i]; xsz = sz;
            } else { ei = (const int*)d_in[i]; esz = sz; }
        }
    }
    if (!x  && n_in > 0) { x  = (const float*)d_in[0]; xsz = in_sizes[0]; }
    if (!ei && n_in > 1) { ei = (const int*)d_in[1];   esz = in_sizes[1]; }
    if (!W  && n_in > 3) W = (const float*)d_in[n_in - 2];
    if (!b  && n_in > 4) b = (const float*)d_in[n_in - 1];

    float* out = (float*)d_out;
    int N = xsz / F;
    int E = esz / 2;
    if (N > N_MAX) N = N_MAX;
    if (E > E_MAX) E = E_MAX;

    detect_kernel<<<1, 256>>>(ei, E);
    hist_kernel<<<(E + 255) / 256, 256>>>(ei, E, N);
    scan_kernel<<<1, 1024>>>(N);
    fill_kernel<<<(E + 255) / 256, 256>>>(ei, E, N);
    fused_kernel<<<(N + 63) / 64, 256>>>((const float2*)x, W, b, out, N);
}

// round 8
// speedup vs baseline: 2.1536x; 2.1536x over previous
#include <cuda_runtime.h>

// ---------------------------------------------------------------------------
// SAGEConv (cugraph, mean agg, concat root):
//   detect -> hist -> region-alloc (atomicAdd, no scan) -> fill
//   -> FUSED agg+GEMM (+cnt zero)
// ---------------------------------------------------------------------------

#define N_MAX 100000
#define E_MAX 1600000
#define F 64
#define KDIM 128
#define APAD 68   // tile row stride (multiple of 4 floats -> 16B-aligned rows)

// Scratch (__device__ globals; zero-initialized at load; g_cnt kept zeroed
// across calls by fused_kernel's epilogue, g_total by detect_kernel)
__device__ int g_cnt[N_MAX];
__device__ int g_rowptr[N_MAX];
__device__ int g_cursor[N_MAX];
__device__ int g_ebuf[E_MAX];
__device__ int g_is64;
__device__ int g_total;

// --------------------------------------------------------------------------
__device__ __forceinline__ int edge_src(const int* ei, int is64, int E, int e, int N) {
    int v = is64 ? ei[2 * e] : ei[e];
    return min(max(v, 0), N - 1);
}
__device__ __forceinline__ int edge_dst(const int* ei, int is64, int E, int e, int N) {
    int v = is64 ? ei[2 * E + 2 * e] : ei[E + e];
    return min(max(v, 0), N - 1);
}

// packed f32x2 helpers (Blackwell sm_10x)
__device__ __forceinline__ unsigned long long ffma2(unsigned long long a,
                                                    unsigned long long b,
                                                    unsigned long long c) {
    unsigned long long d;
    asm("fma.rn.f32x2 %0, %1, %2, %3;" : "=l"(d) : "l"(a), "l"(b), "l"(c));
    return d;
}
__device__ __forceinline__ unsigned long long dup2(float w) {
    unsigned long long r;
    asm("mov.b64 %0, {%1, %1};" : "=l"(r) : "f"(w));
    return r;
}
__device__ __forceinline__ float2 unpack2(unsigned long long v) {
    float2 r;
    asm("mov.b64 {%0, %1}, %2;" : "=f"(r.x), "=f"(r.y) : "l"(v));
    return r;
}

// --------------------------------------------------------------------------
// edge dtype detect + zero the allocation counter
__global__ void detect_kernel(const int* __restrict__ ei, int E) {
    int ok = 1;
    int n = min(E, 2048);
    for (int j = threadIdx.x; j < n; j += blockDim.x)
        if (ei[2 * j + 1] != 0) ok = 0;
    int all_ok = __syncthreads_and(ok);
    if (threadIdx.x == 0) {
        g_is64 = all_ok ? 1 : 0;
        g_total = 0;
    }
}

// histogram of destinations (g_cnt zero on entry — kept by fused epilogue)
__global__ void hist_kernel(const int* __restrict__ ei, int E, int N) {
    int e = blockIdx.x * blockDim.x + threadIdx.x;
    if (e < E) {
        int is64 = g_is64;
        atomicAdd(&g_cnt[edge_dst(ei, is64, E, e, N)], 1);
    }
}

// Region allocation: disjoint contiguous region per node, no ordering needed.
// Uniform-address atomicAdd -> ptxas REDUX warp aggregation (cheap).
__global__ void alloc_kernel(int N) {
    int i = blockIdx.x * blockDim.x + threadIdx.x;
    if (i < N) {
        int c = g_cnt[i];
        int start = atomicAdd(&g_total, c);
        g_rowptr[i] = start;
        g_cursor[i] = start;
    }
}

// bucket fill: ebuf[dst-grouped] = src
__global__ void fill_kernel(const int* __restrict__ ei, int E, int N) {
    int e = blockIdx.x * blockDim.x + threadIdx.x;
    if (e < E) {
        int is64 = g_is64;
        int d = edge_dst(ei, is64, E, e, N);
        int pos = atomicAdd(&g_cursor[d], 1);
        if (pos >= 0 && pos < E_MAX)
            g_ebuf[pos] = edge_src(ei, is64, E, e, N);
    }
}

// --------------------------------------------------------------------------
// Inner 64x64x64 MMA step: packed f32x2, node-pairs in 64-bit accumulators.
__device__ __forceinline__ void mma_tile(const float (*As)[APAD], const float (*Ws)[APAD],
                                         unsigned long long acc[2][4], int tx, int ty) {
    #pragma unroll 8
    for (int k = 0; k < 64; k++) {
        float4 a4 = *(const float4*)&As[k][ty * 4];
        float4 w4 = *(const float4*)&Ws[k][tx * 4];
        unsigned long long a01, a23;
        asm("mov.b64 %0, {%1, %2};" : "=l"(a01) : "f"(a4.x), "f"(a4.y));
        asm("mov.b64 %0, {%1, %2};" : "=l"(a23) : "f"(a4.z), "f"(a4.w));
        float wj[4] = {w4.x, w4.y, w4.z, w4.w};
        #pragma unroll
        for (int j = 0; j < 4; j++) {
            unsigned long long wd = dup2(wj[j]);
            acc[0][j] = ffma2(a01, wd, acc[0][j]);
            acc[1][j] = ffma2(a23, wd, acc[1][j]);
        }
    }
}

// Fused: gather-aggregate (mean) -> concat GEMM + bias; zeroes own g_cnt slice.
__global__ __launch_bounds__(256)
void fused_kernel(const float2* __restrict__ x2,
                  const float*  __restrict__ W,      // [64][128]
                  const float*  __restrict__ bias,   // [64]
                  float* __restrict__ out, int N) {
    __shared__ float As[64][APAD];   // [k][node]
    __shared__ float Ws[64][APAD];   // [k][o]

    int tid  = threadIdx.x;
    int lane = tid & 31, warp = tid >> 5;
    int tx = tid & 15, ty = tid >> 4;
    int n0 = blockIdx.x * 64;

    unsigned long long acc[2][4];
    #pragma unroll
    for (int p = 0; p < 2; p++)
        #pragma unroll
        for (int j = 0; j < 4; j++) acc[p][j] = 0ULL;

    // ---- stage Ws (kt=0) ----
    for (int i = tid; i < 64 * 64; i += 256) {
        int o = i >> 6, k = i & 63;
        Ws[k][o] = W[o * KDIM + k];
    }

    // ---- aggregate: 8 nodes per warp, lane owns feature pair (2l, 2l+1) ----
    for (int t = 0; t < 8; t++) {
        int nloc = warp * 8 + t;
        int node = n0 + nloc;
        float2 a = make_float2(0.f, 0.f);
        float inv = 1.f;
        if (node < N) {
            int start = g_rowptr[node];
            int deg   = g_cnt[node];
            for (int base = 0; base < deg; base += 32) {
                int rem = deg - base;
                int cnt = rem < 32 ? rem : 32;
                int myidx = (lane < cnt) ? g_ebuf[start + base + lane] : 0;
                #pragma unroll 4
                for (int j = 0; j < cnt; j++) {
                    int s = __shfl_sync(0xffffffffu, myidx, j);
                    float2 v = __ldg(x2 + (size_t)s * 32 + lane);
                    a.x += v.x; a.y += v.y;
                }
            }
            inv = 1.0f / (float)(deg > 1 ? deg : 1);
        }
        As[2 * lane][nloc]     = a.x * inv;
        As[2 * lane + 1][nloc] = a.y * inv;
    }
    __syncthreads();

    // ---- MMA kt=0 (agg half) ----
    mma_tile(As, Ws, acc, tx, ty);
    __syncthreads();

    // ---- stage Ws (kt=1) + x tile (transposed) ----
    for (int i = tid; i < 64 * 64; i += 256) {
        int o = i >> 6, k = i & 63;
        Ws[k][o] = W[o * KDIM + 64 + k];
    }
    for (int t = 0; t < 8; t++) {
        int nloc = warp * 8 + t;
        int node = n0 + nloc;
        float2 v = make_float2(0.f, 0.f);
        if (node < N) v = __ldg(x2 + (size_t)node * 32 + lane);
        As[2 * lane][nloc]     = v.x;
        As[2 * lane + 1][nloc] = v.y;
    }
    __syncthreads();

    // ---- MMA kt=1 (self half) ----
    mma_tile(As, Ws, acc, tx, ty);

    // ---- epilogue: +bias, float4 stores ----
    float4 bv = *(const float4*)(bias + tx * 4);
    #pragma unroll
    for (int p = 0; p < 2; p++) {
        float2 c0 = unpack2(acc[p][0]);
        float2 c1 = unpack2(acc[p][1]);
        float2 c2 = unpack2(acc[p][2]);
        float2 c3 = unpack2(acc[p][3]);
        int n = n0 + ty * 4 + 2 * p;
        if (n < N) {
            float4 o4 = make_float4(c0.x + bv.x, c1.x + bv.y, c2.x + bv.z, c3.x + bv.w);
            ((float4*)out)[(size_t)n * 16 + tx] = o4;
        }
        if (n + 1 < N) {
            float4 o4 = make_float4(c0.y + bv.x, c1.y + bv.y, c2.y + bv.z, c3.y + bv.w);
            ((float4*)out)[(size_t)(n + 1) * 16 + tx] = o4;
        }
    }

    // ---- zero own g_cnt slice for the next call ----
    if (tid < 64) {
        int n = n0 + tid;
        if (n < N) g_cnt[n] = 0;
    }
}

// --------------------------------------------------------------------------
extern "C" void kernel_launch(void* const* d_in, const int* in_sizes, int n_in,
                              void* d_out, int out_size) {
    const float* x  = nullptr;
    const int*   ei = nullptr;
    const float* W  = nullptr;
    const float* b  = nullptr;
    int xsz = 0, esz = 0;

    for (int i = 0; i < n_in; i++) {
        int sz = in_sizes[i];
        if (sz == 64) b = (const float*)d_in[i];
        else if (sz == 8192) W = (const float*)d_in[i];
        else if (sz <= 2) { /* num_nodes scalar */ }
        else {
            if (sz > xsz) {
                if (x) { ei = (const int*)x; esz = xsz; }
                x = (const float*)d_in[i]; xsz = sz;
            } else { ei = (const int*)d_in[i]; esz = sz; }
        }
    }
    if (!x  && n_in > 0) { x  = (const float*)d_in[0]; xsz = in_sizes[0]; }
    if (!ei && n_in > 1) { ei = (const int*)d_in[1];   esz = in_sizes[1]; }
    if (!W  && n_in > 3) W = (const float*)d_in[n_in - 2];
    if (!b  && n_in > 4) b = (const float*)d_in[n_in - 1];

    float* out = (float*)d_out;
    int N = xsz / F;
    int E = esz / 2;
    if (N > N_MAX) N = N_MAX;
    if (E > E_MAX) E = E_MAX;

    detect_kernel<<<1, 256>>>(ei, E);
    hist_kernel<<<(E + 255) / 256, 256>>>(ei, E, N);
    alloc_kernel<<<(N + 255) / 256, 256>>>(N);
    fill_kernel<<<(E + 255) / 256, 256>>>(ei, E, N);
    fused_kernel<<<(N + 63) / 64, 256>>>((const float2*)x, W, b, out, N);
}

// round 10
// speedup vs baseline: 2.1867x; 1.0154x over previous
#include <cuda_runtime.h>

// ---------------------------------------------------------------------------
// SAGEConv (cugraph, mean agg, concat root):
//   hist(+detect, +total reset) -> region-alloc -> fill (4 edges/thread)
//   -> FUSED agg (2-edge float4 gather) + concat GEMM (+cnt zero)
// ---------------------------------------------------------------------------

#define N_MAX 100000
#define E_MAX 1600000
#define F 64
#define KDIM 128
#define APAD 68   // tile row stride (multiple of 4 floats -> 16B-aligned rows)

// Scratch (__device__ globals; zero-initialized at load; g_cnt kept zeroed
// across calls by fused_kernel's epilogue, g_total by hist_kernel block 0)
__device__ int g_cnt[N_MAX];
__device__ int g_rowptr[N_MAX];
__device__ int g_cursor[N_MAX];
__device__ int g_ebuf[E_MAX];
__device__ int g_is64;
__device__ int g_total;

// --------------------------------------------------------------------------
__device__ __forceinline__ int edge_src(const int* ei, int is64, int E, int e, int N) {
    int v = is64 ? ei[2 * e] : ei[e];
    return min(max(v, 0), N - 1);
}
__device__ __forceinline__ int edge_dst(const int* ei, int is64, int E, int e, int N) {
    int v = is64 ? ei[2 * E + 2 * e] : ei[E + e];
    return min(max(v, 0), N - 1);
}

// Block-local edge dtype detect: int64 values < 2^31 -> hi words all zero.
__device__ __forceinline__ int detect_is64(const int* ei, int E) {
    __shared__ int s_is64;
    int ok = 1;
    int n = min(E, 128);
    if (threadIdx.x < n && ei[2 * threadIdx.x + 1] != 0) ok = 0;
    int all_ok = __syncthreads_and(ok);
    if (threadIdx.x == 0) s_is64 = all_ok ? 1 : 0;
    __syncthreads();
    return s_is64;
}

// packed f32x2 helpers (Blackwell sm_10x)
__device__ __forceinline__ unsigned long long ffma2(unsigned long long a,
                                                    unsigned long long b,
                                                    unsigned long long c) {
    unsigned long long d;
    asm("fma.rn.f32x2 %0, %1, %2, %3;" : "=l"(d) : "l"(a), "l"(b), "l"(c));
    return d;
}
__device__ __forceinline__ unsigned long long dup2(float w) {
    unsigned long long r;
    asm("mov.b64 %0, {%1, %1};" : "=l"(r) : "f"(w));
    return r;
}
__device__ __forceinline__ float2 unpack2(unsigned long long v) {
    float2 r;
    asm("mov.b64 {%0, %1}, %2;" : "=f"(r.x), "=f"(r.y) : "l"(v));
    return r;
}

// --------------------------------------------------------------------------
// histogram of destinations, 4 edges/thread (g_cnt zero on entry).
// Block 0: publish g_is64 AND reset g_total for this call (determinism
// across graph replays — R9's crash was a missing g_total reset).
__global__ void hist_kernel(const int* __restrict__ ei, int E, int N) {
    int is64 = detect_is64(ei, E);
    if (blockIdx.x == 0 && threadIdx.x == 0) {
        g_is64 = is64;
        g_total = 0;
    }
    int t = blockIdx.x * blockDim.x + threadIdx.x;
    #pragma unroll
    for (int r = 0; r < 4; r++) {
        int e = t * 4 + r;
        if (e < E) atomicAdd(&g_cnt[edge_dst(ei, is64, E, e, N)], 1);
    }
}

// Region allocation: disjoint contiguous region per node (order irrelevant).
__global__ void alloc_kernel(int N) {
    int i = blockIdx.x * blockDim.x + threadIdx.x;
    if (i < N) {
        int c = g_cnt[i];
        int start = atomicAdd(&g_total, c);
        g_rowptr[i] = start;
        g_cursor[i] = start;
    }
}

// bucket fill, 4 edges/thread for atomic-latency MLP
__global__ void fill_kernel(const int* __restrict__ ei, int E, int N) {
    int is64 = g_is64;
    int t = blockIdx.x * blockDim.x + threadIdx.x;
    #pragma unroll
    for (int r = 0; r < 4; r++) {
        int e = t * 4 + r;
        if (e < E) {
            int d = edge_dst(ei, is64, E, e, N);
            int pos = atomicAdd(&g_cursor[d], 1);
            if (pos >= 0 && pos < E_MAX)
                g_ebuf[pos] = edge_src(ei, is64, E, e, N);
        }
    }
}

// --------------------------------------------------------------------------
// Inner 64x64x64 MMA step: packed f32x2, node-pairs in 64-bit accumulators.
__device__ __forceinline__ void mma_tile(const float (*As)[APAD], const float (*Ws)[APAD],
                                         unsigned long long acc[2][4], int tx, int ty) {
    #pragma unroll 8
    for (int k = 0; k < 64; k++) {
        float4 a4 = *(const float4*)&As[k][ty * 4];
        float4 w4 = *(const float4*)&Ws[k][tx * 4];
        unsigned long long a01, a23;
        asm("mov.b64 %0, {%1, %2};" : "=l"(a01) : "f"(a4.x), "f"(a4.y));
        asm("mov.b64 %0, {%1, %2};" : "=l"(a23) : "f"(a4.z), "f"(a4.w));
        float wj[4] = {w4.x, w4.y, w4.z, w4.w};
        #pragma unroll
        for (int j = 0; j < 4; j++) {
            unsigned long long wd = dup2(wj[j]);
            acc[0][j] = ffma2(a01, wd, acc[0][j]);
            acc[1][j] = ffma2(a23, wd, acc[1][j]);
        }
    }
}

// Fused: gather-aggregate (mean, 2 edges in flight/warp) -> concat GEMM + bias.
__global__ __launch_bounds__(256)
void fused_kernel(const float4* __restrict__ x4,
                  const float*  __restrict__ W,      // [64][128]
                  const float*  __restrict__ bias,   // [64]
                  float* __restrict__ out, int N) {
    __shared__ float As[64][APAD];   // [k][node]
    __shared__ float Ws[64][APAD];   // [k][o]

    int tid  = threadIdx.x;
    int lane = tid & 31, warp = tid >> 5;
    int half = lane >> 4, sub = lane & 15;   // gather: 16 lanes per edge row
    int tx = tid & 15, ty = tid >> 4;
    int n0 = blockIdx.x * 64;

    unsigned long long acc[2][4];
    #pragma unroll
    for (int p = 0; p < 2; p++)
        #pragma unroll
        for (int j = 0; j < 4; j++) acc[p][j] = 0ULL;

    // ---- stage Ws (kt=0) ----
    for (int i = tid; i < 64 * 64; i += 256) {
        int o = i >> 6, k = i & 63;
        Ws[k][o] = W[o * KDIM + k];
    }

    // ---- aggregate: 8 nodes/warp; half-warps take edges j and j+1 ----
    for (int t = 0; t < 8; t++) {
        int nloc = warp * 8 + t;
        int node = n0 + nloc;
        float4 a = make_float4(0.f, 0.f, 0.f, 0.f);
        float inv = 1.f;
        if (node < N) {
            int deg   = g_cnt[node];
            int start = g_rowptr[node];
            start = min(start, E_MAX - deg);          // defensive: no OOB reads
            start = max(start, 0);
            for (int base = 0; base < deg; base += 32) {
                int rem = deg - base;
                int cnt = rem < 32 ? rem : 32;
                int myidx = (lane < cnt) ? g_ebuf[start + base + lane] : 0;
                #pragma unroll 4
                for (int j = 0; j < cnt; j += 2) {
                    int e = j + half;
                    int s = __shfl_sync(0xffffffffu, myidx, e & 31);
                    if (e < cnt) {
                        float4 v = __ldg(x4 + (size_t)s * 16 + sub);
                        a.x += v.x; a.y += v.y; a.z += v.z; a.w += v.w;
                    }
                }
            }
            // combine the two half-warp partial sums
            a.x += __shfl_xor_sync(0xffffffffu, a.x, 16);
            a.y += __shfl_xor_sync(0xffffffffu, a.y, 16);
            a.z += __shfl_xor_sync(0xffffffffu, a.z, 16);
            a.w += __shfl_xor_sync(0xffffffffu, a.w, 16);
            inv = 1.0f / (float)(deg > 1 ? deg : 1);
        }
        if (half == 0) {
            As[4 * sub + 0][nloc] = a.x * inv;
            As[4 * sub + 1][nloc] = a.y * inv;
            As[4 * sub + 2][nloc] = a.z * inv;
            As[4 * sub + 3][nloc] = a.w * inv;
        }
    }
    __syncthreads();

    // ---- MMA kt=0 (agg half) ----
    mma_tile(As, Ws, acc, tx, ty);
    __syncthreads();

    // ---- stage Ws (kt=1) + x tile (transposed) ----
    for (int i = tid; i < 64 * 64; i += 256) {
        int o = i >> 6, k = i & 63;
        Ws[k][o] = W[o * KDIM + 64 + k];
    }
    for (int t = half; t < 8; t += 2) {          // 2 nodes in flight per warp
        int nloc = warp * 8 + t;
        int node = n0 + nloc;
        float4 v = make_float4(0.f, 0.f, 0.f, 0.f);
        if (node < N) v = __ldg(x4 + (size_t)node * 16 + sub);
        As[4 * sub + 0][nloc] = v.x;
        As[4 * sub + 1][nloc] = v.y;
        As[4 * sub + 2][nloc] = v.z;
        As[4 * sub + 3][nloc] = v.w;
    }
    __syncthreads();

    // ---- MMA kt=1 (self half) ----
    mma_tile(As, Ws, acc, tx, ty);

    // ---- epilogue: +bias, float4 stores ----
    float4 bv = *(const float4*)(bias + tx * 4);
    #pragma unroll
    for (int p = 0; p < 2; p++) {
        float2 c0 = unpack2(acc[p][0]);
        float2 c1 = unpack2(acc[p][1]);
        float2 c2 = unpack2(acc[p][2]);
        float2 c3 = unpack2(acc[p][3]);
        int n = n0 + ty * 4 + 2 * p;
        if (n < N) {
            float4 o4 = make_float4(c0.x + bv.x, c1.x + bv.y, c2.x + bv.z, c3.x + bv.w);
            ((float4*)out)[(size_t)n * 16 + tx] = o4;
        }
        if (n + 1 < N) {
            float4 o4 = make_float4(c0.y + bv.x, c1.y + bv.y, c2.y + bv.z, c3.y + bv.w);
            ((float4*)out)[(size_t)(n + 1) * 16 + tx] = o4;
        }
    }

    // ---- zero own g_cnt slice for the next call ----
    if (tid < 64) {
        int n = n0 + tid;
        if (n < N) g_cnt[n] = 0;
    }
}

// --------------------------------------------------------------------------
extern "C" void kernel_launch(void* const* d_in, const int* in_sizes, int n_in,
                              void* d_out, int out_size) {
    const float* x  = nullptr;
    const int*   ei = nullptr;
    const float* W  = nullptr;
    const float* b  = nullptr;
    int xsz = 0, esz = 0;

    for (int i = 0; i < n_in; i++) {
        int sz = in_sizes[i];
        if (sz == 64) b = (const float*)d_in[i];
        else if (sz == 8192) W = (const float*)d_in[i];
        else if (sz <= 2) { /* num_nodes scalar */ }
        else {
            if (sz > xsz) {
                if (x) { ei = (const int*)x; esz = xsz; }
                x = (const float*)d_in[i]; xsz = sz;
            } else { ei = (const int*)d_in[i]; esz = sz; }
        }
    }
    if (!x  && n_in > 0) { x  = (const float*)d_in[0]; xsz = in_sizes[0]; }
    if (!ei && n_in > 1) { ei = (const int*)d_in[1];   esz = in_sizes[1]; }
    if (!W  && n_in > 3) W = (const float*)d_in[n_in - 2];
    if (!b  && n_in > 4) b = (const float*)d_in[n_in - 1];

    float* out = (float*)d_out;
    int N = xsz / F;
    int E = esz / 2;
    if (N > N_MAX) N = N_MAX;
    if (E > E_MAX) E = E_MAX;

    int et = (E + 3) / 4;   // 4 edges per thread
    hist_kernel<<<(et + 255) / 256, 256>>>(ei, E, N);
    alloc_kernel<<<(N + 255) / 256, 256>>>(N);
    fill_kernel<<<(et + 255) / 256, 256>>>(ei, E, N);
    fused_kernel<<<(N + 63) / 64, 256>>>((const float4*)x, W, b, out, N);
}

// round 11
// speedup vs baseline: 2.3324x; 1.0666x over previous
#include <cuda_runtime.h>

// ---------------------------------------------------------------------------
// SAGEConv (cugraph, mean agg, concat root):
//   hist(+detect,+total reset) -> alloc(+W transpose) -> fill (4 edges/thr)
//   -> FUSED agg (2-edge float4 gather) + concat GEMM (conflict-free staging)
// ---------------------------------------------------------------------------

#define N_MAX 100000
#define E_MAX 1600000
#define F 64
#define KDIM 128
#define APAD 68   // tile row stride (multiple of 4 floats -> 16B-aligned rows)

// Scratch (__device__ globals; zero-initialized at load; g_cnt kept zeroed
// across calls by fused_kernel's epilogue, g_total by hist_kernel block 0)
__device__ int g_cnt[N_MAX];
__device__ int g_rowptr[N_MAX];
__device__ int g_cursor[N_MAX];
__device__ int g_ebuf[E_MAX];
__device__ int g_is64;
__device__ int g_total;
__device__ __align__(16) float g_Wt[KDIM * F];   // W transposed: [k][o]

// --------------------------------------------------------------------------
__device__ __forceinline__ int edge_src(const int* ei, int is64, int E, int e, int N) {
    int v = is64 ? ei[2 * e] : ei[e];
    return min(max(v, 0), N - 1);
}
__device__ __forceinline__ int edge_dst(const int* ei, int is64, int E, int e, int N) {
    int v = is64 ? ei[2 * E + 2 * e] : ei[E + e];
    return min(max(v, 0), N - 1);
}

// Block-local edge dtype detect: int64 values < 2^31 -> hi words all zero.
__device__ __forceinline__ int detect_is64(const int* ei, int E) {
    __shared__ int s_is64;
    int ok = 1;
    int n = min(E, 128);
    if (threadIdx.x < n && ei[2 * threadIdx.x + 1] != 0) ok = 0;
    int all_ok = __syncthreads_and(ok);
    if (threadIdx.x == 0) s_is64 = all_ok ? 1 : 0;
    __syncthreads();
    return s_is64;
}

// packed f32x2 helpers (Blackwell sm_10x)
__device__ __forceinline__ unsigned long long ffma2(unsigned long long a,
                                                    unsigned long long b,
                                                    unsigned long long c) {
    unsigned long long d;
    asm("fma.rn.f32x2 %0, %1, %2, %3;" : "=l"(d) : "l"(a), "l"(b), "l"(c));
    return d;
}
__device__ __forceinline__ unsigned long long dup2(float w) {
    unsigned long long r;
    asm("mov.b64 %0, {%1, %1};" : "=l"(r) : "f"(w));
    return r;
}
__device__ __forceinline__ float2 unpack2(unsigned long long v) {
    float2 r;
    asm("mov.b64 {%0, %1}, %2;" : "=f"(r.x), "=f"(r.y) : "l"(v));
    return r;
}

// --------------------------------------------------------------------------
// histogram of destinations, 4 edges/thread. Block 0 publishes g_is64 and
// resets g_total (determinism across graph replays).
__global__ void hist_kernel(const int* __restrict__ ei, int E, int N) {
    int is64 = detect_is64(ei, E);
    if (blockIdx.x == 0 && threadIdx.x == 0) {
        g_is64 = is64;
        g_total = 0;
    }
    int t = blockIdx.x * blockDim.x + threadIdx.x;
    #pragma unroll
    for (int r = 0; r < 4; r++) {
        int e = t * 4 + r;
        if (e < E) atomicAdd(&g_cnt[edge_dst(ei, is64, E, e, N)], 1);
    }
}

// Region allocation + W transpose (first 8192 threads): g_Wt[k][o] = W[o][k].
__global__ void alloc_kernel(int N, const float* __restrict__ W) {
    int i = blockIdx.x * blockDim.x + threadIdx.x;
    if (i < KDIM * F) {
        int k = i >> 6, o = i & 63;
        g_Wt[k * F + o] = W[o * KDIM + k];
    }
    if (i < N) {
        int c = g_cnt[i];
        int start = atomicAdd(&g_total, c);
        g_rowptr[i] = start;
        g_cursor[i] = start;
    }
}

// bucket fill, 4 edges/thread for atomic-latency MLP
__global__ void fill_kernel(const int* __restrict__ ei, int E, int N) {
    int is64 = g_is64;
    int t = blockIdx.x * blockDim.x + threadIdx.x;
    #pragma unroll
    for (int r = 0; r < 4; r++) {
        int e = t * 4 + r;
        if (e < E) {
            int d = edge_dst(ei, is64, E, e, N);
            int pos = atomicAdd(&g_cursor[d], 1);
            if (pos >= 0 && pos < E_MAX)
                g_ebuf[pos] = edge_src(ei, is64, E, e, N);
        }
    }
}

// --------------------------------------------------------------------------
// Inner 64x64x64 MMA step: packed f32x2, node-pairs in 64-bit accumulators.
// As read = warp-broadcast (1 wavefront), Ws read = 256B consecutive (2).
__device__ __forceinline__ void mma_tile(const float (*As)[APAD], const float (*Ws)[APAD],
                                         unsigned long long acc[2][4], int tx, int ty) {
    #pragma unroll 8
    for (int k = 0; k < 64; k++) {
        float4 a4 = *(const float4*)&As[k][ty * 4];
        float4 w4 = *(const float4*)&Ws[k][tx * 4];
        unsigned long long a01, a23;
        asm("mov.b64 %0, {%1, %2};" : "=l"(a01) : "f"(a4.x), "f"(a4.y));
        asm("mov.b64 %0, {%1, %2};" : "=l"(a23) : "f"(a4.z), "f"(a4.w));
        float wj[4] = {w4.x, w4.y, w4.z, w4.w};
        #pragma unroll
        for (int j = 0; j < 4; j++) {
            unsigned long long wd = dup2(wj[j]);
            acc[0][j] = ffma2(a01, wd, acc[0][j]);
            acc[1][j] = ffma2(a23, wd, acc[1][j]);
        }
    }
}

// Conflict-free Ws staging from pre-transposed g_Wt (coalesced LDG + f4 STS).
__device__ __forceinline__ void stage_ws(float (*Ws)[APAD], int kt, int tid) {
    const float4* src = (const float4*)(g_Wt + kt * 64 * F);
    for (int i = tid; i < 64 * 16; i += 256) {
        int k = i >> 4, c4 = i & 15;
        *(float4*)&Ws[k][c4 * 4] = src[i];
    }
}

// Fused: gather-aggregate (mean, 2 edges in flight/warp) -> concat GEMM + bias.
__global__ __launch_bounds__(256)
void fused_kernel(const float4* __restrict__ x4,
                  const float*  __restrict__ bias,   // [64]
                  float* __restrict__ out, int N) {
    __shared__ float As[64][APAD];   // [k][node]
    __shared__ float Ws[64][APAD];   // [k][o]

    int tid  = threadIdx.x;
    int lane = tid & 31, warp = tid >> 5;
    int half = lane >> 4, sub = lane & 15;   // gather: 16 lanes per edge row
    int tx = tid & 15, ty = tid >> 4;
    int n0 = blockIdx.x * 64;

    unsigned long long acc[2][4];
    #pragma unroll
    for (int p = 0; p < 2; p++)
        #pragma unroll
        for (int j = 0; j < 4; j++) acc[p][j] = 0ULL;

    // ---- stage Ws (kt=0) ----
    stage_ws(Ws, 0, tid);

    // ---- aggregate: 8 nodes/warp; half-warps take edges j and j+1 ----
    for (int t = 0; t < 8; t++) {
        int nloc = warp * 8 + t;
        int node = n0 + nloc;
        float4 a = make_float4(0.f, 0.f, 0.f, 0.f);
        float inv = 1.f;
        if (node < N) {
            int deg   = g_cnt[node];
            int start = g_rowptr[node];
            start = min(start, E_MAX - deg);          // defensive: no OOB reads
            start = max(start, 0);
            for (int base = 0; base < deg; base += 32) {
                int rem = deg - base;
                int cnt = rem < 32 ? rem : 32;
                int myidx = (lane < cnt) ? g_ebuf[start + base + lane] : 0;
                #pragma unroll 4
                for (int j = 0; j < cnt; j += 2) {
                    int e = j + half;
                    int s = __shfl_sync(0xffffffffu, myidx, e & 31);
                    if (e < cnt) {
                        float4 v = __ldg(x4 + (size_t)s * 16 + sub);
                        a.x += v.x; a.y += v.y; a.z += v.z; a.w += v.w;
                    }
                }
            }
            // combine the two half-warp partial sums (both halves get full sum)
            a.x += __shfl_xor_sync(0xffffffffu, a.x, 16);
            a.y += __shfl_xor_sync(0xffffffffu, a.y, 16);
            a.z += __shfl_xor_sync(0xffffffffu, a.z, 16);
            a.w += __shfl_xor_sync(0xffffffffu, a.w, 16);
            inv = 1.0f / (float)(deg > 1 ? deg : 1);
        }
        // both halves store: half 0 -> components x,y ; half 1 -> z,w
        float v0 = half ? a.z : a.x;
        float v1 = half ? a.w : a.y;
        As[4 * sub + 2 * half + 0][nloc] = v0 * inv;
        As[4 * sub + 2 * half + 1][nloc] = v1 * inv;
    }
    __syncthreads();

    // ---- MMA kt=0 (agg half) ----
    mma_tile(As, Ws, acc, tx, ty);
    __syncthreads();

    // ---- stage Ws (kt=1) + x tile (transposed, both halves store) ----
    stage_ws(Ws, 1, tid);
    for (int t = 0; t < 8; t++) {
        int nloc = warp * 8 + t;
        int node = n0 + nloc;
        float4 v = make_float4(0.f, 0.f, 0.f, 0.f);
        if (node < N) v = __ldg(x4 + (size_t)node * 16 + sub);  // halves dup, L1 broadcast
        float v0 = half ? v.z : v.x;
        float v1 = half ? v.w : v.y;
        As[4 * sub + 2 * half + 0][nloc] = v0;
        As[4 * sub + 2 * half + 1][nloc] = v1;
    }
    __syncthreads();

    // ---- MMA kt=1 (self half) ----
    mma_tile(As, Ws, acc, tx, ty);

    // ---- epilogue: +bias, float4 stores ----
    float4 bv = *(const float4*)(bias + tx * 4);
    #pragma unroll
    for (int p = 0; p < 2; p++) {
        float2 c0 = unpack2(acc[p][0]);
        float2 c1 = unpack2(acc[p][1]);
        float2 c2 = unpack2(acc[p][2]);
        float2 c3 = unpack2(acc[p][3]);
        int n = n0 + ty * 4 + 2 * p;
        if (n < N) {
            float4 o4 = make_float4(c0.x + bv.x, c1.x + bv.y, c2.x + bv.z, c3.x + bv.w);
            ((float4*)out)[(size_t)n * 16 + tx] = o4;
        }
        if (n + 1 < N) {
            float4 o4 = make_float4(c0.y + bv.x, c1.y + bv.y, c2.y + bv.z, c3.y + bv.w);
            ((float4*)out)[(size_t)(n + 1) * 16 + tx] = o4;
        }
    }

    // ---- zero own g_cnt slice for the next call ----
    if (tid < 64) {
        int n = n0 + tid;
        if (n < N) g_cnt[n] = 0;
    }
}

// --------------------------------------------------------------------------
extern "C" void kernel_launch(void* const* d_in, const int* in_sizes, int n_in,
                              void* d_out, int out_size) {
    const float* x  = nullptr;
    const int*   ei = nullptr;
    const float* W  = nullptr;
    const float* b  = nullptr;
    int xsz = 0, esz = 0;

    for (int i = 0; i < n_in; i++) {
        int sz = in_sizes[i];
        if (sz == 64) b = (const float*)d_in[i];
        else if (sz == 8192) W = (const float*)d_in[i];
        else if (sz <= 2) { /* num_nodes scalar */ }
        else {
            if (sz > xsz) {
                if (x) { ei = (const int*)x; esz = xsz; }
                x = (const float*)d_in[i]; xsz = sz;
            } else { ei = (const int*)d_in[i]; esz = sz; }
        }
    }
    if (!x  && n_in > 0) { x  = (const float*)d_in[0]; xsz = in_sizes[0]; }
    if (!ei && n_in > 1) { ei = (const int*)d_in[1];   esz = in_sizes[1]; }
    if (!W  && n_in > 3) W = (const float*)d_in[n_in - 2];
    if (!b  && n_in > 4) b = (const float*)d_in[n_in - 1];

    float* out = (float*)d_out;
    int N = xsz / F;
    int E = esz / 2;
    if (N > N_MAX) N = N_MAX;
    if (E > E_MAX) E = E_MAX;

    int et = (E + 3) / 4;   // 4 edges per thread
    hist_kernel<<<(et + 255) / 256, 256>>>(ei, E, N);
    alloc_kernel<<<(N + 255) / 256, 256>>>(N, W);
    fill_kernel<<<(et + 255) / 256, 256>>>(ei, E, N);
    fused_kernel<<<(N + 63) / 64, 256>>>((const float4*)x, b, out, N);
}

// round 13
// speedup vs baseline: 2.3588x; 1.0113x over previous
#include <cuda_runtime.h>

// ---------------------------------------------------------------------------
// SAGEConv (cugraph, mean agg, concat root):
//   hist(+detect,+total reset) -> alloc(+W transpose) -> fill (4 edges/thr)
//   -> FUSED agg + concat GEMM. A-tile row-major [node][k] (conflict-free),
//      f32x2 accumulators packed over column pairs.
// ---------------------------------------------------------------------------

#define N_MAX 100000
#define E_MAX 1600000
#define F 64
#define KDIM 128
#define APAD 68   // A-tile stride: multiple of 4 floats -> 16B-aligned rows
                  // (R12 used 66 -> odd rows 8B-aligned -> misaligned trap)

// Scratch (__device__ globals; zero-initialized at load; g_cnt kept zeroed
// across calls by fused_kernel's epilogue, g_total by hist_kernel block 0)
__device__ int g_cnt[N_MAX];
__device__ int g_rowptr[N_MAX];
__device__ int g_cursor[N_MAX];
__device__ int g_ebuf[E_MAX];
__device__ int g_is64;
__device__ int g_total;
__device__ __align__(16) float g_Wt[KDIM * F];   // W transposed: [k][o]

// --------------------------------------------------------------------------
__device__ __forceinline__ int edge_src(const int* ei, int is64, int E, int e, int N) {
    int v = is64 ? ei[2 * e] : ei[e];
    return min(max(v, 0), N - 1);
}
__device__ __forceinline__ int edge_dst(const int* ei, int is64, int E, int e, int N) {
    int v = is64 ? ei[2 * E + 2 * e] : ei[E + e];
    return min(max(v, 0), N - 1);
}

// Block-local edge dtype detect: int64 values < 2^31 -> hi words all zero.
__device__ __forceinline__ int detect_is64(const int* ei, int E) {
    __shared__ int s_is64;
    int ok = 1;
    int n = min(E, 128);
    if (threadIdx.x < n && ei[2 * threadIdx.x + 1] != 0) ok = 0;
    int all_ok = __syncthreads_and(ok);
    if (threadIdx.x == 0) s_is64 = all_ok ? 1 : 0;
    __syncthreads();
    return s_is64;
}

// packed f32x2 helpers (Blackwell sm_10x)
__device__ __forceinline__ unsigned long long ffma2(unsigned long long a,
                                                    unsigned long long b,
                                                    unsigned long long c) {
    unsigned long long d;
    asm("fma.rn.f32x2 %0, %1, %2, %3;" : "=l"(d) : "l"(a), "l"(b), "l"(c));
    return d;
}
__device__ __forceinline__ unsigned long long dup2(float w) {
    unsigned long long r;
    asm("mov.b64 %0, {%1, %1};" : "=l"(r) : "f"(w));
    return r;
}
__device__ __forceinline__ unsigned long long pack2(float lo, float hi) {
    unsigned long long r;
    asm("mov.b64 %0, {%1, %2};" : "=l"(r) : "f"(lo), "f"(hi));
    return r;
}
__device__ __forceinline__ float2 unpack2(unsigned long long v) {
    float2 r;
    asm("mov.b64 {%0, %1}, %2;" : "=f"(r.x), "=f"(r.y) : "l"(v));
    return r;
}

// --------------------------------------------------------------------------
// histogram of destinations, 4 edges/thread. Block 0 publishes g_is64 and
// resets g_total (determinism across graph replays).
__global__ void hist_kernel(const int* __restrict__ ei, int E, int N) {
    int is64 = detect_is64(ei, E);
    if (blockIdx.x == 0 && threadIdx.x == 0) {
        g_is64 = is64;
        g_total = 0;
    }
    int t = blockIdx.x * blockDim.x + threadIdx.x;
    #pragma unroll
    for (int r = 0; r < 4; r++) {
        int e = t * 4 + r;
        if (e < E) atomicAdd(&g_cnt[edge_dst(ei, is64, E, e, N)], 1);
    }
}

// Region allocation + W transpose (first 8192 threads): g_Wt[k][o] = W[o][k].
__global__ void alloc_kernel(int N, const float* __restrict__ W) {
    int i = blockIdx.x * blockDim.x + threadIdx.x;
    if (i < KDIM * F) {
        int k = i >> 6, o = i & 63;
        g_Wt[k * F + o] = W[o * KDIM + k];
    }
    if (i < N) {
        int c = g_cnt[i];
        int start = atomicAdd(&g_total, c);
        g_rowptr[i] = start;
        g_cursor[i] = start;
    }
}

// bucket fill, 4 edges/thread for atomic-latency MLP
__global__ void fill_kernel(const int* __restrict__ ei, int E, int N) {
    int is64 = g_is64;
    int t = blockIdx.x * blockDim.x + threadIdx.x;
    #pragma unroll
    for (int r = 0; r < 4; r++) {
        int e = t * 4 + r;
        if (e < E) {
            int d = edge_dst(ei, is64, E, e, N);
            int pos = atomicAdd(&g_cursor[d], 1);
            if (pos >= 0 && pos < E_MAX)
                g_ebuf[pos] = edge_src(ei, is64, E, e, N);
        }
    }
}

// --------------------------------------------------------------------------
// Inner 64x64x64 MMA: A row-major [node][k], accumulators packed over
// column pairs. Per 2-k step: 4 LDS.64 (A, broadcast) + 2 LDS.128 (W).
__device__ __forceinline__ void mma_tile(const float (*As)[APAD], const float (*Ws)[64],
                                         unsigned long long acc[4][2], int tx, int ty) {
    #pragma unroll 4
    for (int k = 0; k < 64; k += 2) {
        float4 w0 = *(const float4*)&Ws[k][tx * 4];
        float4 w1 = *(const float4*)&Ws[k + 1][tx * 4];
        unsigned long long w0a = pack2(w0.x, w0.y), w0b = pack2(w0.z, w0.w);
        unsigned long long w1a = pack2(w1.x, w1.y), w1b = pack2(w1.z, w1.w);
        float2 a[4];
        #pragma unroll
        for (int i = 0; i < 4; i++)
            a[i] = *(const float2*)&As[ty * 4 + i][k];
        #pragma unroll
        for (int i = 0; i < 4; i++) {
            unsigned long long a0 = dup2(a[i].x);
            unsigned long long a1 = dup2(a[i].y);
            acc[i][0] = ffma2(w0a, a0, acc[i][0]);
            acc[i][1] = ffma2(w0b, a0, acc[i][1]);
            acc[i][0] = ffma2(w1a, a1, acc[i][0]);
            acc[i][1] = ffma2(w1b, a1, acc[i][1]);
        }
    }
}

// Conflict-free Ws staging from pre-transposed g_Wt (coalesced LDG + f4 STS).
__device__ __forceinline__ void stage_ws(float (*Ws)[64], int kt, int tid) {
    const float4* src = (const float4*)(g_Wt + kt * 64 * F);
    for (int i = tid; i < 64 * 16; i += 256) {
        int k = i >> 4, c4 = i & 15;
        *(float4*)&Ws[k][c4 * 4] = src[i];
    }
}

// Fused: gather-aggregate (mean, 2 edges in flight/warp) -> concat GEMM + bias.
__global__ __launch_bounds__(256)
void fused_kernel(const float4* __restrict__ x4,
                  const float*  __restrict__ bias,   // [64]
                  float* __restrict__ out, int N) {
    __shared__ float As[64][APAD];   // [node][k]  row-major
    __shared__ float Ws[64][64];     // [k][o]

    int tid  = threadIdx.x;
    int lane = tid & 31, warp = tid >> 5;
    int half = lane >> 4, sub = lane & 15;   // gather: 16 lanes per edge row
    int tx = tid & 15, ty = tid >> 4;
    int n0 = blockIdx.x * 64;

    unsigned long long acc[4][2];
    #pragma unroll
    for (int i = 0; i < 4; i++) { acc[i][0] = 0ULL; acc[i][1] = 0ULL; }

    // ---- stage Ws (kt=0) ----
    stage_ws(Ws, 0, tid);

    // ---- aggregate: 8 nodes/warp; half-warps take edges j and j+1 ----
    for (int t = 0; t < 8; t++) {
        int nloc = warp * 8 + t;
        int node = n0 + nloc;
        float4 a = make_float4(0.f, 0.f, 0.f, 0.f);
        float inv = 1.f;
        if (node < N) {
            int deg   = g_cnt[node];
            int start = g_rowptr[node];
            start = min(start, E_MAX - deg);          // defensive: no OOB reads
            start = max(start, 0);
            for (int base = 0; base < deg; base += 32) {
                int rem = deg - base;
                int cnt = rem < 32 ? rem : 32;
                int myidx = (lane < cnt) ? g_ebuf[start + base + lane] : 0;
                #pragma unroll 4
                for (int j = 0; j < cnt; j += 2) {
                    int e = j + half;
                    int s = __shfl_sync(0xffffffffu, myidx, e & 31);
                    if (e < cnt) {
                        float4 v = __ldg(x4 + (size_t)s * 16 + sub);
                        a.x += v.x; a.y += v.y; a.z += v.z; a.w += v.w;
                    }
                }
            }
            // combine the two half-warp partial sums (both halves get full sum)
            a.x += __shfl_xor_sync(0xffffffffu, a.x, 16);
            a.y += __shfl_xor_sync(0xffffffffu, a.y, 16);
            a.z += __shfl_xor_sync(0xffffffffu, a.z, 16);
            a.w += __shfl_xor_sync(0xffffffffu, a.w, 16);
            inv = 1.0f / (float)(deg > 1 ? deg : 1);
        }
        // row-major write: contiguous float4 per lane -> conflict-free
        if (half == 0) {
            float4 st = make_float4(a.x * inv, a.y * inv, a.z * inv, a.w * inv);
            *(float4*)&As[nloc][4 * sub] = st;
        }
    }
    __syncthreads();

    // ---- MMA kt=0 (agg half) ----
    mma_tile(As, Ws, acc, tx, ty);
    __syncthreads();

    // ---- stage Ws (kt=1) + x tile (row-major, 2 nodes in flight) ----
    stage_ws(Ws, 1, tid);
    for (int t = half; t < 8; t += 2) {
        int nloc = warp * 8 + t;
        int node = n0 + nloc;
        float4 v = make_float4(0.f, 0.f, 0.f, 0.f);
        if (node < N) v = __ldg(x4 + (size_t)node * 16 + sub);
        *(float4*)&As[nloc][4 * sub] = v;
    }
    __syncthreads();

    // ---- MMA kt=1 (self half) ----
    mma_tile(As, Ws, acc, tx, ty);

    // ---- epilogue: +bias, float4 stores (thread owns 4 full node rows) ----
    float4 bv = *(const float4*)(bias + tx * 4);
    #pragma unroll
    for (int i = 0; i < 4; i++) {
        int n = n0 + ty * 4 + i;
        if (n < N) {
            float2 lo = unpack2(acc[i][0]);
            float2 hi = unpack2(acc[i][1]);
            float4 o4 = make_float4(lo.x + bv.x, lo.y + bv.y, hi.x + bv.z, hi.y + bv.w);
            ((float4*)out)[(size_t)n * 16 + tx] = o4;
        }
    }

    // ---- zero own g_cnt slice for the next call ----
    if (tid < 64) {
        int n = n0 + tid;
        if (n < N) g_cnt[n] = 0;
    }
}

// --------------------------------------------------------------------------
extern "C" void kernel_launch(void* const* d_in, const int* in_sizes, int n_in,
                              void* d_out, int out_size) {
    const float* x  = nullptr;
    const int*   ei = nullptr;
    const float* W  = nullptr;
    const float* b  = nullptr;
    int xsz = 0, esz = 0;

    for (int i = 0; i < n_in; i++) {
        int sz = in_sizes[i];
        if (sz == 64) b = (const float*)d_in[i];
        else if (sz == 8192) W = (const float*)d_in[i];
        else if (sz <= 2) { /* num_nodes scalar */ }
        else {
            if (sz > xsz) {
                if (x) { ei = (const int*)x; esz = xsz; }
                x = (const float*)d_in[i]; xsz = sz;
            } else { ei = (const int*)d_in[i]; esz = sz; }
        }
    }
    if (!x  && n_in > 0) { x  = (const float*)d_in[0]; xsz = in_sizes[0]; }
    if (!ei && n_in > 1) { ei = (const int*)d_in[1];   esz = in_sizes[1]; }
    if (!W  && n_in > 3) W = (const float*)d_in[n_in - 2];
    if (!b  && n_in > 4) b = (const float*)d_in[n_in - 1];

    float* out = (float*)d_out;
    int N = xsz / F;
    int E = esz / 2;
    if (N > N_MAX) N = N_MAX;
    if (E > E_MAX) E = E_MAX;

    int et = (E + 3) / 4;   // 4 edges per thread
    hist_kernel<<<(et + 255) / 256, 256>>>(ei, E, N);
    alloc_kernel<<<(N + 255) / 256, 256>>>(N, W);
    fill_kernel<<<(et + 255) / 256, 256>>>(ei, E, N);
    fused_kernel<<<(N + 63) / 64, 256>>>((const float4*)x, b, out, N);
}

// round 14
// speedup vs baseline: 2.4095x; 1.0215x over previous
#include <cuda_runtime.h>

// ---------------------------------------------------------------------------
// SAGEConv (cugraph, mean agg, concat root):
//   hist(+detect,+total reset) -> alloc(+W transpose) -> fill (4 edges/thr)
//   -> FUSED agg + concat GEMM. Row-major A-tile, f32x2 column-pair accs,
//      5 blocks/SM, lane-parallel node metadata.
// ---------------------------------------------------------------------------

#define N_MAX 100000
#define E_MAX 1600000
#define F 64
#define KDIM 128
#define APAD 68   // A-tile stride: multiple of 4 floats -> 16B-aligned rows

// Scratch (__device__ globals; zero-initialized at load; g_cnt kept zeroed
// across calls by fused_kernel's epilogue, g_total by hist_kernel block 0)
__device__ int g_cnt[N_MAX];
__device__ int g_rowptr[N_MAX];
__device__ int g_cursor[N_MAX];
__device__ int g_ebuf[E_MAX];
__device__ int g_is64;
__device__ int g_total;
__device__ __align__(16) float g_Wt[KDIM * F];   // W transposed: [k][o]

// --------------------------------------------------------------------------
__device__ __forceinline__ int edge_src(const int* ei, int is64, int E, int e, int N) {
    int v = is64 ? ei[2 * e] : ei[e];
    return min(max(v, 0), N - 1);
}
__device__ __forceinline__ int edge_dst(const int* ei, int is64, int E, int e, int N) {
    int v = is64 ? ei[2 * E + 2 * e] : ei[E + e];
    return min(max(v, 0), N - 1);
}

// Block-local edge dtype detect: int64 values < 2^31 -> hi words all zero.
__device__ __forceinline__ int detect_is64(const int* ei, int E) {
    __shared__ int s_is64;
    int ok = 1;
    int n = min(E, 128);
    if (threadIdx.x < n && ei[2 * threadIdx.x + 1] != 0) ok = 0;
    int all_ok = __syncthreads_and(ok);
    if (threadIdx.x == 0) s_is64 = all_ok ? 1 : 0;
    __syncthreads();
    return s_is64;
}

// packed f32x2 helpers (Blackwell sm_10x)
__device__ __forceinline__ unsigned long long ffma2(unsigned long long a,
                                                    unsigned long long b,
                                                    unsigned long long c) {
    unsigned long long d;
    asm("fma.rn.f32x2 %0, %1, %2, %3;" : "=l"(d) : "l"(a), "l"(b), "l"(c));
    return d;
}
__device__ __forceinline__ unsigned long long dup2(float w) {
    unsigned long long r;
    asm("mov.b64 %0, {%1, %1};" : "=l"(r) : "f"(w));
    return r;
}
__device__ __forceinline__ unsigned long long pack2(float lo, float hi) {
    unsigned long long r;
    asm("mov.b64 %0, {%1, %2};" : "=l"(r) : "f"(lo), "f"(hi));
    return r;
}
__device__ __forceinline__ float2 unpack2(unsigned long long v) {
    float2 r;
    asm("mov.b64 {%0, %1}, %2;" : "=f"(r.x), "=f"(r.y) : "l"(v));
    return r;
}

// --------------------------------------------------------------------------
// histogram of destinations, 4 edges/thread. Block 0 publishes g_is64 and
// resets g_total (determinism across graph replays).
__global__ void hist_kernel(const int* __restrict__ ei, int E, int N) {
    int is64 = detect_is64(ei, E);
    if (blockIdx.x == 0 && threadIdx.x == 0) {
        g_is64 = is64;
        g_total = 0;
    }
    int t = blockIdx.x * blockDim.x + threadIdx.x;
    #pragma unroll
    for (int r = 0; r < 4; r++) {
        int e = t * 4 + r;
        if (e < E) atomicAdd(&g_cnt[edge_dst(ei, is64, E, e, N)], 1);
    }
}

// Region allocation + W transpose (first 8192 threads): g_Wt[k][o] = W[o][k].
__global__ void alloc_kernel(int N, const float* __restrict__ W) {
    int i = blockIdx.x * blockDim.x + threadIdx.x;
    if (i < KDIM * F) {
        int k = i >> 6, o = i & 63;
        g_Wt[k * F + o] = W[o * KDIM + k];
    }
    if (i < N) {
        int c = g_cnt[i];
        int start = atomicAdd(&g_total, c);
        g_rowptr[i] = start;
        g_cursor[i] = start;
    }
}

// bucket fill, 4 edges/thread for atomic-latency MLP
__global__ void fill_kernel(const int* __restrict__ ei, int E, int N) {
    int is64 = g_is64;
    int t = blockIdx.x * blockDim.x + threadIdx.x;
    #pragma unroll
    for (int r = 0; r < 4; r++) {
        int e = t * 4 + r;
        if (e < E) {
            int d = edge_dst(ei, is64, E, e, N);
            int pos = atomicAdd(&g_cursor[d], 1);
            if (pos >= 0 && pos < E_MAX)
                g_ebuf[pos] = edge_src(ei, is64, E, e, N);
        }
    }
}

// --------------------------------------------------------------------------
// Inner 64x64x64 MMA: A row-major [node][k], accumulators packed over
// column pairs. Per 2-k step: 4 LDS.64 (A, broadcast) + 2 LDS.128 (W).
__device__ __forceinline__ void mma_tile(const float (*As)[APAD], const float (*Ws)[64],
                                         unsigned long long acc[4][2], int tx, int ty) {
    #pragma unroll 4
    for (int k = 0; k < 64; k += 2) {
        float4 w0 = *(const float4*)&Ws[k][tx * 4];
        float4 w1 = *(const float4*)&Ws[k + 1][tx * 4];
        unsigned long long w0a = pack2(w0.x, w0.y), w0b = pack2(w0.z, w0.w);
        unsigned long long w1a = pack2(w1.x, w1.y), w1b = pack2(w1.z, w1.w);
        float2 a[4];
        #pragma unroll
        for (int i = 0; i < 4; i++)
            a[i] = *(const float2*)&As[ty * 4 + i][k];
        #pragma unroll
        for (int i = 0; i < 4; i++) {
            unsigned long long a0 = dup2(a[i].x);
            unsigned long long a1 = dup2(a[i].y);
            acc[i][0] = ffma2(w0a, a0, acc[i][0]);
            acc[i][1] = ffma2(w0b, a0, acc[i][1]);
            acc[i][0] = ffma2(w1a, a1, acc[i][0]);
            acc[i][1] = ffma2(w1b, a1, acc[i][1]);
        }
    }
}

// Conflict-free Ws staging from pre-transposed g_Wt (coalesced LDG + f4 STS).
__device__ __forceinline__ void stage_ws(float (*Ws)[64], int kt, int tid) {
    const float4* src = (const float4*)(g_Wt + kt * 64 * F);
    for (int i = tid; i < 64 * 16; i += 256) {
        int k = i >> 4, c4 = i & 15;
        *(float4*)&Ws[k][c4 * 4] = src[i];
    }
}

// Fused: gather-aggregate (mean, 2 edges in flight/warp) -> concat GEMM + bias.
// 5 blocks/SM (regs fit at 51): latency-bound gather needs the warps.
__global__ __launch_bounds__(256, 5)
void fused_kernel(const float4* __restrict__ x4,
                  const float*  __restrict__ bias,   // [64]
                  float* __restrict__ out, int N) {
    __shared__ float As[64][APAD];   // [node][k]  row-major
    __shared__ float Ws[64][64];     // [k][o]

    int tid  = threadIdx.x;
    int lane = tid & 31, warp = tid >> 5;
    int half = lane >> 4, sub = lane & 15;   // gather: 16 lanes per edge row
    int tx = tid & 15, ty = tid >> 4;
    int n0 = blockIdx.x * 64;

    unsigned long long acc[4][2];
    #pragma unroll
    for (int i = 0; i < 4; i++) { acc[i][0] = 0ULL; acc[i][1] = 0ULL; }

    // ---- stage Ws (kt=0) ----
    stage_ws(Ws, 0, tid);

    // ---- lane-parallel metadata: lanes 0..7 fetch (deg,start) for the
    //      warp's 8 nodes in 2 coalesced loads (kills 16 serial L2 trips) ----
    int myDeg = 0, myStart = 0;
    {
        int nd = n0 + warp * 8 + lane;
        if (lane < 8 && nd < N) {
            myDeg   = g_cnt[nd];
            myStart = g_rowptr[nd];
        }
    }

    // ---- aggregate: 8 nodes/warp; half-warps take edges j and j+1 ----
    for (int t = 0; t < 8; t++) {
        int nloc = warp * 8 + t;
        int node = n0 + nloc;
        int deg   = __shfl_sync(0xffffffffu, myDeg, t);
        int start = __shfl_sync(0xffffffffu, myStart, t);
        float4 a = make_float4(0.f, 0.f, 0.f, 0.f);
        float inv = 1.f;
        if (node < N) {
            start = min(start, E_MAX - deg);          // defensive: no OOB reads
            start = max(start, 0);
            for (int base = 0; base < deg; base += 32) {
                int rem = deg - base;
                int cnt = rem < 32 ? rem : 32;
                int myidx = (lane < cnt) ? g_ebuf[start + base + lane] : 0;
                #pragma unroll 4
                for (int j = 0; j < cnt; j += 2) {
                    int e = j + half;
                    int s = __shfl_sync(0xffffffffu, myidx, e & 31);
                    if (e < cnt) {
                        float4 v = __ldg(x4 + (size_t)s * 16 + sub);
                        a.x += v.x; a.y += v.y; a.z += v.z; a.w += v.w;
                    }
                }
            }
            // combine the two half-warp partial sums
            a.x += __shfl_xor_sync(0xffffffffu, a.x, 16);
            a.y += __shfl_xor_sync(0xffffffffu, a.y, 16);
            a.z += __shfl_xor_sync(0xffffffffu, a.z, 16);
            a.w += __shfl_xor_sync(0xffffffffu, a.w, 16);
            inv = 1.0f / (float)(deg > 1 ? deg : 1);
        }
        // row-major write: contiguous float4 per lane -> conflict-free
        if (half == 0) {
            float4 st = make_float4(a.x * inv, a.y * inv, a.z * inv, a.w * inv);
            *(float4*)&As[nloc][4 * sub] = st;
        }
    }
    __syncthreads();

    // ---- MMA kt=0 (agg half) ----
    mma_tile(As, Ws, acc, tx, ty);
    __syncthreads();

    // ---- stage Ws (kt=1) + x tile (row-major, 2 nodes in flight) ----
    stage_ws(Ws, 1, tid);
    for (int t = half; t < 8; t += 2) {
        int nloc = warp * 8 + t;
        int node = n0 + nloc;
        float4 v = make_float4(0.f, 0.f, 0.f, 0.f);
        if (node < N) v = __ldg(x4 + (size_t)node * 16 + sub);
        *(float4*)&As[nloc][4 * sub] = v;
    }
    __syncthreads();

    // ---- MMA kt=1 (self half) ----
    mma_tile(As, Ws, acc, tx, ty);

    // ---- epilogue: +bias, float4 stores (thread owns 4 full node rows) ----
    float4 bv = *(const float4*)(bias + tx * 4);
    #pragma unroll
    for (int i = 0; i < 4; i++) {
        int n = n0 + ty * 4 + i;
        if (n < N) {
            float2 lo = unpack2(acc[i][0]);
            float2 hi = unpack2(acc[i][1]);
            float4 o4 = make_float4(lo.x + bv.x, lo.y + bv.y, hi.x + bv.z, hi.y + bv.w);
            ((float4*)out)[(size_t)n * 16 + tx] = o4;
        }
    }

    // ---- zero own g_cnt slice for the next call ----
    if (tid < 64) {
        int n = n0 + tid;
        if (n < N) g_cnt[n] = 0;
    }
}

// --------------------------------------------------------------------------
extern "C" void kernel_launch(void* const* d_in, const int* in_sizes, int n_in,
                              void* d_out, int out_size) {
    const float* x  = nullptr;
    const int*   ei = nullptr;
    const float* W  = nullptr;
    const float* b  = nullptr;
    int xsz = 0, esz = 0;

    for (int i = 0; i < n_in; i++) {
        int sz = in_sizes[i];
        if (sz == 64) b = (const float*)d_in[i];
        else if (sz == 8192) W = (const float*)d_in[i];
        else if (sz <= 2) { /* num_nodes scalar */ }
        else {
            if (sz > xsz) {
                if (x) { ei = (const int*)x; esz = xsz; }
                x = (const float*)d_in[i]; xsz = sz;
            } else { ei = (const int*)d_in[i]; esz = sz; }
        }
    }
    if (!x  && n_in > 0) { x  = (const float*)d_in[0]; xsz = in_sizes[0]; }
    if (!ei && n_in > 1) { ei = (const int*)d_in[1];   esz = in_sizes[1]; }
    if (!W  && n_in > 3) W = (const float*)d_in[n_in - 2];
    if (!b  && n_in > 4) b = (const float*)d_in[n_in - 1];

    float* out = (float*)d_out;
    int N = xsz / F;
    int E = esz / 2;
    if (N > N_MAX) N = N_MAX;
    if (E > E_MAX) E = E_MAX;

    int et = (E + 3) / 4;   // 4 edges per thread
    hist_kernel<<<(et + 255) / 256, 256>>>(ei, E, N);
    alloc_kernel<<<(N + 255) / 256, 256>>>(N, W);
    fill_kernel<<<(et + 255) / 256, 256>>>(ei, E, N);
    fused_kernel<<<(N + 63) / 64, 256>>>((const float4*)x, b, out, N);
}

// round 15
// speedup vs baseline: 2.4464x; 1.0153x over previous
#include <cuda_runtime.h>

// ---------------------------------------------------------------------------
// SAGEConv (cugraph, mean agg, concat root):
//   hist(+detect,+total reset) -> alloc(+W transpose) -> fill (4 edges/thr)
//   -> FUSED agg (4-edge MLP gather) + concat GEMM (f32x2), 5 blocks/SM.
// ---------------------------------------------------------------------------

#define N_MAX 100000
#define E_MAX 1600000
#define F 64
#define KDIM 128
#define APAD 68   // A-tile stride: multiple of 4 floats -> 16B-aligned rows

// Scratch (__device__ globals; zero-initialized at load; g_cnt kept zeroed
// across calls by fused_kernel's epilogue, g_total by hist_kernel block 0)
__device__ int g_cnt[N_MAX];
__device__ int g_rowptr[N_MAX];
__device__ int g_cursor[N_MAX];
__device__ int g_ebuf[E_MAX];
__device__ int g_is64;
__device__ int g_total;
__device__ __align__(16) float g_Wt[KDIM * F];   // W transposed: [k][o]

// --------------------------------------------------------------------------
__device__ __forceinline__ int edge_src(const int* ei, int is64, int E, int e, int N) {
    int v = is64 ? ei[2 * e] : ei[e];
    return min(max(v, 0), N - 1);
}
__device__ __forceinline__ int edge_dst(const int* ei, int is64, int E, int e, int N) {
    int v = is64 ? ei[2 * E + 2 * e] : ei[E + e];
    return min(max(v, 0), N - 1);
}

// Block-local edge dtype detect: int64 values < 2^31 -> hi words all zero.
__device__ __forceinline__ int detect_is64(const int* ei, int E) {
    __shared__ int s_is64;
    int ok = 1;
    int n = min(E, 128);
    if (threadIdx.x < n && ei[2 * threadIdx.x + 1] != 0) ok = 0;
    int all_ok = __syncthreads_and(ok);
    if (threadIdx.x == 0) s_is64 = all_ok ? 1 : 0;
    __syncthreads();
    return s_is64;
}

// packed f32x2 helpers (Blackwell sm_10x)
__device__ __forceinline__ unsigned long long ffma2(unsigned long long a,
                                                    unsigned long long b,
                                                    unsigned long long c) {
    unsigned long long d;
    asm("fma.rn.f32x2 %0, %1, %2, %3;" : "=l"(d) : "l"(a), "l"(b), "l"(c));
    return d;
}
__device__ __forceinline__ unsigned long long dup2(float w) {
    unsigned long long r;
    asm("mov.b64 %0, {%1, %1};" : "=l"(r) : "f"(w));
    return r;
}
__device__ __forceinline__ unsigned long long pack2(float lo, float hi) {
    unsigned long long r;
    asm("mov.b64 %0, {%1, %2};" : "=l"(r) : "f"(lo), "f"(hi));
    return r;
}
__device__ __forceinline__ float2 unpack2(unsigned long long v) {
    float2 r;
    asm("mov.b64 {%0, %1}, %2;" : "=f"(r.x), "=f"(r.y) : "l"(v));
    return r;
}

// --------------------------------------------------------------------------
// histogram of destinations, 4 edges/thread. Block 0 publishes g_is64 and
// resets g_total (determinism across graph replays).
__global__ void hist_kernel(const int* __restrict__ ei, int E, int N) {
    int is64 = detect_is64(ei, E);
    if (blockIdx.x == 0 && threadIdx.x == 0) {
        g_is64 = is64;
        g_total = 0;
    }
    int t = blockIdx.x * blockDim.x + threadIdx.x;
    #pragma unroll
    for (int r = 0; r < 4; r++) {
        int e = t * 4 + r;
        if (e < E) atomicAdd(&g_cnt[edge_dst(ei, is64, E, e, N)], 1);
    }
}

// Region allocation + W transpose (first 8192 threads): g_Wt[k][o] = W[o][k].
__global__ void alloc_kernel(int N, const float* __restrict__ W) {
    int i = blockIdx.x * blockDim.x + threadIdx.x;
    if (i < KDIM * F) {
        int k = i >> 6, o = i & 63;
        g_Wt[k * F + o] = W[o * KDIM + k];
    }
    if (i < N) {
        int c = g_cnt[i];
        int start = atomicAdd(&g_total, c);
        g_rowptr[i] = start;
        g_cursor[i] = start;
    }
}

// bucket fill, 4 edges/thread for atomic-latency MLP
__global__ void fill_kernel(const int* __restrict__ ei, int E, int N) {
    int is64 = g_is64;
    int t = blockIdx.x * blockDim.x + threadIdx.x;
    #pragma unroll
    for (int r = 0; r < 4; r++) {
        int e = t * 4 + r;
        if (e < E) {
            int d = edge_dst(ei, is64, E, e, N);
            int pos = atomicAdd(&g_cursor[d], 1);
            if (pos >= 0 && pos < E_MAX)
                g_ebuf[pos] = edge_src(ei, is64, E, e, N);
        }
    }
}

// --------------------------------------------------------------------------
// Inner 64x64x64 MMA: A row-major [node][k], accumulators packed over
// column pairs. Per 2-k step: 4 LDS.64 (A, broadcast) + 2 LDS.128 (W).
__device__ __forceinline__ void mma_tile(const float (*As)[APAD], const float (*Ws)[64],
                                         unsigned long long acc[4][2], int tx, int ty) {
    #pragma unroll 4
    for (int k = 0; k < 64; k += 2) {
        float4 w0 = *(const float4*)&Ws[k][tx * 4];
        float4 w1 = *(const float4*)&Ws[k + 1][tx * 4];
        unsigned long long w0a = pack2(w0.x, w0.y), w0b = pack2(w0.z, w0.w);
        unsigned long long w1a = pack2(w1.x, w1.y), w1b = pack2(w1.z, w1.w);
        float2 a[4];
        #pragma unroll
        for (int i = 0; i < 4; i++)
            a[i] = *(const float2*)&As[ty * 4 + i][k];
        #pragma unroll
        for (int i = 0; i < 4; i++) {
            unsigned long long a0 = dup2(a[i].x);
            unsigned long long a1 = dup2(a[i].y);
            acc[i][0] = ffma2(w0a, a0, acc[i][0]);
            acc[i][1] = ffma2(w0b, a0, acc[i][1]);
            acc[i][0] = ffma2(w1a, a1, acc[i][0]);
            acc[i][1] = ffma2(w1b, a1, acc[i][1]);
        }
    }
}

// Conflict-free Ws staging from pre-transposed g_Wt (coalesced LDG + f4 STS).
__device__ __forceinline__ void stage_ws(float (*Ws)[64], int kt, int tid) {
    const float4* src = (const float4*)(g_Wt + kt * 64 * F);
    for (int i = tid; i < 64 * 16; i += 256) {
        int k = i >> 4, c4 = i & 15;
        *(float4*)&Ws[k][c4 * 4] = src[i];
    }
}

// Fused: gather-aggregate (mean, 4 edges in flight/warp) -> concat GEMM + bias.
__global__ __launch_bounds__(256, 5)
void fused_kernel(const float4* __restrict__ x4,
                  const float*  __restrict__ bias,   // [64]
                  float* __restrict__ out, int N) {
    __shared__ float As[64][APAD];   // [node][k]  row-major
    __shared__ float Ws[64][64];     // [k][o]

    int tid  = threadIdx.x;
    int lane = tid & 31, warp = tid >> 5;
    int half = lane >> 4, sub = lane & 15;   // gather: 16 lanes per edge row
    int tx = tid & 15, ty = tid >> 4;
    int n0 = blockIdx.x * 64;

    unsigned long long acc[4][2];
    #pragma unroll
    for (int i = 0; i < 4; i++) { acc[i][0] = 0ULL; acc[i][1] = 0ULL; }

    // ---- stage Ws (kt=0) ----
    stage_ws(Ws, 0, tid);

    // ---- lane-parallel metadata: lanes 0..7 fetch (deg,start) ----
    int myDeg = 0, myStart = 0;
    {
        int nd = n0 + warp * 8 + lane;
        if (lane < 8 && nd < N) {
            myDeg   = g_cnt[nd];
            myStart = g_rowptr[nd];
        }
    }

    // ---- aggregate: 8 nodes/warp; each half-warp keeps 2 edges in flight ----
    for (int t = 0; t < 8; t++) {
        int nloc = warp * 8 + t;
        int node = n0 + nloc;
        int deg   = __shfl_sync(0xffffffffu, myDeg, t);
        int start = __shfl_sync(0xffffffffu, myStart, t);
        float4 a0 = make_float4(0.f, 0.f, 0.f, 0.f);
        float4 a1 = make_float4(0.f, 0.f, 0.f, 0.f);
        float inv = 1.f;
        if (node < N) {
            start = min(start, E_MAX - deg);          // defensive: no OOB reads
            start = max(start, 0);
            for (int base = 0; base < deg; base += 32) {
                int rem = deg - base;
                int cnt = rem < 32 ? rem : 32;
                int myidx = (lane < cnt) ? g_ebuf[start + base + lane] : 0;
                #pragma unroll 2
                for (int j = 0; j < cnt; j += 4) {
                    int e0 = j + half;       // half0: j,   half1: j+1
                    int e1 = j + 2 + half;   // half0: j+2, half1: j+3
                    int s0 = __shfl_sync(0xffffffffu, myidx, e0 & 31);
                    int s1 = __shfl_sync(0xffffffffu, myidx, e1 & 31);
                    if (e0 < cnt) {
                        float4 v = __ldg(x4 + (size_t)s0 * 16 + sub);
                        a0.x += v.x; a0.y += v.y; a0.z += v.z; a0.w += v.w;
                    }
                    if (e1 < cnt) {
                        float4 v = __ldg(x4 + (size_t)s1 * 16 + sub);
                        a1.x += v.x; a1.y += v.y; a1.z += v.z; a1.w += v.w;
                    }
                }
            }
            a0.x += a1.x; a0.y += a1.y; a0.z += a1.z; a0.w += a1.w;
            // combine the two half-warp partial sums
            a0.x += __shfl_xor_sync(0xffffffffu, a0.x, 16);
            a0.y += __shfl_xor_sync(0xffffffffu, a0.y, 16);
            a0.z += __shfl_xor_sync(0xffffffffu, a0.z, 16);
            a0.w += __shfl_xor_sync(0xffffffffu, a0.w, 16);
            inv = 1.0f / (float)(deg > 1 ? deg : 1);
        }
        // row-major write: contiguous float4 per lane -> conflict-free
        if (half == 0) {
            float4 st = make_float4(a0.x * inv, a0.y * inv, a0.z * inv, a0.w * inv);
            *(float4*)&As[nloc][4 * sub] = st;
        }
    }
    __syncthreads();

    // ---- MMA kt=0 (agg half) ----
    mma_tile(As, Ws, acc, tx, ty);
    __syncthreads();

    // ---- stage Ws (kt=1) + x tile (row-major, 2 nodes in flight) ----
    stage_ws(Ws, 1, tid);
    for (int t = half; t < 8; t += 2) {
        int nloc = warp * 8 + t;
        int node = n0 + nloc;
        float4 v = make_float4(0.f, 0.f, 0.f, 0.f);
        if (node < N) v = __ldg(x4 + (size_t)node * 16 + sub);
        *(float4*)&As[nloc][4 * sub] = v;
    }
    __syncthreads();

    // ---- MMA kt=1 (self half) ----
    mma_tile(As, Ws, acc, tx, ty);

    // ---- epilogue: +bias, float4 stores (thread owns 4 full node rows) ----
    float4 bv = *(const float4*)(bias + tx * 4);
    #pragma unroll
    for (int i = 0; i < 4; i++) {
        int n = n0 + ty * 4 + i;
        if (n < N) {
            float2 lo = unpack2(acc[i][0]);
            float2 hi = unpack2(acc[i][1]);
            float4 o4 = make_float4(lo.x + bv.x, lo.y + bv.y, hi.x + bv.z, hi.y + bv.w);
            ((float4*)out)[(size_t)n * 16 + tx] = o4;
        }
    }

    // ---- zero own g_cnt slice for the next call ----
    if (tid < 64) {
        int n = n0 + tid;
        if (n < N) g_cnt[n] = 0;
    }
}

// --------------------------------------------------------------------------
extern "C" void kernel_launch(void* const* d_in, const int* in_sizes, int n_in,
                              void* d_out, int out_size) {
    const float* x  = nullptr;
    const int*   ei = nullptr;
    const float* W  = nullptr;
    const float* b  = nullptr;
    int xsz = 0, esz = 0;

    for (int i = 0; i < n_in; i++) {
        int sz = in_sizes[i];
        if (sz == 64) b = (const float*)d_in[i];
        else if (sz == 8192) W = (const float*)d_in[i];
        else if (sz <= 2) { /* num_nodes scalar */ }
        else {
            if (sz > xsz) {
                if (x) { ei = (const int*)x; esz = xsz; }
                x = (const float*)d_in[i]; xsz = sz;
            } else { ei = (const int*)d_in[i]; esz = sz; }
        }
    }
    if (!x  && n_in > 0) { x  = (const float*)d_in[0]; xsz = in_sizes[0]; }
    if (!ei && n_in > 1) { ei = (const int*)d_in[1];   esz = in_sizes[1]; }
    if (!W  && n_in > 3) W = (const float*)d_in[n_in - 2];
    if (!b  && n_in > 4) b = (const float*)d_in[n_in - 1];

    float* out = (float*)d_out;
    int N = xsz / F;
    int E = esz / 2;
    if (N > N_MAX) N = N_MAX;
    if (E > E_MAX) E = E_MAX;

    int et = (E + 3) / 4;   // 4 edges per thread
    hist_kernel<<<(et + 255) / 256, 256>>>(ei, E, N);
    alloc_kernel<<<(N + 255) / 256, 256>>>(N, W);
    fill_kernel<<<(et + 255) / 256, 256>>>(ei, E, N);
    fused_kernel<<<(N + 63) / 64, 256>>>((const float4*)x, b, out, N);
}

// round 17
// speedup vs baseline: 2.6387x; 1.0786x over previous
#include <cuda_runtime.h>

// ---------------------------------------------------------------------------
// SAGEConv (cugraph, mean agg, concat root):
//   hist(+detect,+total reset) -> alloc(+W transpose) -> fill (4 edges/thr)
//   -> FUSED agg (half-warp per node, segment-masked shuffles) + concat GEMM.
// ---------------------------------------------------------------------------

#define N_MAX 100000
#define E_MAX 1600000
#define F 64
#define KDIM 128
#define APAD 68   // A-tile stride: multiple of 4 floats -> 16B-aligned rows

// Scratch (__device__ globals; zero-initialized at load; g_cnt kept zeroed
// across calls by fused_kernel's epilogue, g_total by hist_kernel block 0)
__device__ int g_cnt[N_MAX];
__device__ int g_rowptr[N_MAX];
__device__ int g_cursor[N_MAX];
__device__ int g_ebuf[E_MAX];
__device__ int g_is64;
__device__ int g_total;
__device__ __align__(16) float g_Wt[KDIM * F];   // W transposed: [k][o]

// --------------------------------------------------------------------------
__device__ __forceinline__ int edge_src(const int* ei, int is64, int E, int e, int N) {
    int v = is64 ? ei[2 * e] : ei[e];
    return min(max(v, 0), N - 1);
}
__device__ __forceinline__ int edge_dst(const int* ei, int is64, int E, int e, int N) {
    int v = is64 ? ei[2 * E + 2 * e] : ei[E + e];
    return min(max(v, 0), N - 1);
}

// Block-local edge dtype detect: int64 values < 2^31 -> hi words all zero.
__device__ __forceinline__ int detect_is64(const int* ei, int E) {
    __shared__ int s_is64;
    int ok = 1;
    int n = min(E, 128);
    if (threadIdx.x < n && ei[2 * threadIdx.x + 1] != 0) ok = 0;
    int all_ok = __syncthreads_and(ok);
    if (threadIdx.x == 0) s_is64 = all_ok ? 1 : 0;
    __syncthreads();
    return s_is64;
}

// packed f32x2 helpers (Blackwell sm_10x)
__device__ __forceinline__ unsigned long long ffma2(unsigned long long a,
                                                    unsigned long long b,
                                                    unsigned long long c) {
    unsigned long long d;
    asm("fma.rn.f32x2 %0, %1, %2, %3;" : "=l"(d) : "l"(a), "l"(b), "l"(c));
    return d;
}
__device__ __forceinline__ unsigned long long dup2(float w) {
    unsigned long long r;
    asm("mov.b64 %0, {%1, %1};" : "=l"(r) : "f"(w));
    return r;
}
__device__ __forceinline__ unsigned long long pack2(float lo, float hi) {
    unsigned long long r;
    asm("mov.b64 %0, {%1, %2};" : "=l"(r) : "f"(lo), "f"(hi));
    return r;
}
__device__ __forceinline__ float2 unpack2(unsigned long long v) {
    float2 r;
    asm("mov.b64 {%0, %1}, %2;" : "=f"(r.x), "=f"(r.y) : "l"(v));
    return r;
}

// --------------------------------------------------------------------------
// histogram of destinations, 4 edges/thread. Block 0 publishes g_is64 and
// resets g_total (determinism across graph replays).
__global__ void hist_kernel(const int* __restrict__ ei, int E, int N) {
    int is64 = detect_is64(ei, E);
    if (blockIdx.x == 0 && threadIdx.x == 0) {
        g_is64 = is64;
        g_total = 0;
    }
    int t = blockIdx.x * blockDim.x + threadIdx.x;
    #pragma unroll
    for (int r = 0; r < 4; r++) {
        int e = t * 4 + r;
        if (e < E) atomicAdd(&g_cnt[edge_dst(ei, is64, E, e, N)], 1);
    }
}

// Region allocation + W transpose (first 8192 threads): g_Wt[k][o] = W[o][k].
__global__ void alloc_kernel(int N, const float* __restrict__ W) {
    int i = blockIdx.x * blockDim.x + threadIdx.x;
    if (i < KDIM * F) {
        int k = i >> 6, o = i & 63;
        g_Wt[k * F + o] = W[o * KDIM + k];
    }
    if (i < N) {
        int c = g_cnt[i];
        int start = atomicAdd(&g_total, c);
        g_rowptr[i] = start;
        g_cursor[i] = start;
    }
}

// bucket fill, 4 edges/thread for atomic-latency MLP
__global__ void fill_kernel(const int* __restrict__ ei, int E, int N) {
    int is64 = g_is64;
    int t = blockIdx.x * blockDim.x + threadIdx.x;
    #pragma unroll
    for (int r = 0; r < 4; r++) {
        int e = t * 4 + r;
        if (e < E) {
            int d = edge_dst(ei, is64, E, e, N);
            int pos = atomicAdd(&g_cursor[d], 1);
            if (pos >= 0 && pos < E_MAX)
                g_ebuf[pos] = edge_src(ei, is64, E, e, N);
        }
    }
}

// --------------------------------------------------------------------------
// Inner 64x64x64 MMA: A row-major [node][k], accumulators packed over
// column pairs. Per 2-k step: 4 LDS.64 (A, broadcast) + 2 LDS.128 (W).
__device__ __forceinline__ void mma_tile(const float (*As)[APAD], const float (*Ws)[64],
                                         unsigned long long acc[4][2], int tx, int ty) {
    #pragma unroll 4
    for (int k = 0; k < 64; k += 2) {
        float4 w0 = *(const float4*)&Ws[k][tx * 4];
        float4 w1 = *(const float4*)&Ws[k + 1][tx * 4];
        unsigned long long w0a = pack2(w0.x, w0.y), w0b = pack2(w0.z, w0.w);
        unsigned long long w1a = pack2(w1.x, w1.y), w1b = pack2(w1.z, w1.w);
        float2 a[4];
        #pragma unroll
        for (int i = 0; i < 4; i++)
            a[i] = *(const float2*)&As[ty * 4 + i][k];
        #pragma unroll
        for (int i = 0; i < 4; i++) {
            unsigned long long a0 = dup2(a[i].x);
            unsigned long long a1 = dup2(a[i].y);
            acc[i][0] = ffma2(w0a, a0, acc[i][0]);
            acc[i][1] = ffma2(w0b, a0, acc[i][1]);
            acc[i][0] = ffma2(w1a, a1, acc[i][0]);
            acc[i][1] = ffma2(w1b, a1, acc[i][1]);
        }
    }
}

// Conflict-free Ws staging from pre-transposed g_Wt (coalesced LDG + f4 STS).
__device__ __forceinline__ void stage_ws(float (*Ws)[64], int kt, int tid) {
    const float4* src = (const float4*)(g_Wt + kt * 64 * F);
    for (int i = tid; i < 64 * 16; i += 256) {
        int k = i >> 4, c4 = i & 15;
        *(float4*)&Ws[k][c4 * 4] = src[i];
    }
}

// Fused: gather-aggregate (half-warp per node, segment-masked shuffles,
// 4 accumulators -> 8 loads in flight per warp) -> concat GEMM + bias.
__global__ __launch_bounds__(256, 4)
void fused_kernel(const float4* __restrict__ x4,
                  const float*  __restrict__ bias,   // [64]
                  float* __restrict__ out, int N) {
    __shared__ float As[64][APAD];   // [node][k]  row-major
    __shared__ float Ws[64][64];     // [k][o]

    int tid  = threadIdx.x;
    int lane = tid & 31, warp = tid >> 5;
    int half = lane >> 4, sub = lane & 15;   // 16 lanes own one node row
    int tx = tid & 15, ty = tid >> 4;
    int n0 = blockIdx.x * 64;

    // segment mask: the 16 lanes of this half-warp (convergent by construction)
    unsigned hmask = 0xFFFFu << (16 * half);

    unsigned long long acc[4][2];
    #pragma unroll
    for (int i = 0; i < 4; i++) { acc[i][0] = 0ULL; acc[i][1] = 0ULL; }

    // ---- stage Ws (kt=0) ----
    stage_ws(Ws, 0, tid);

    // ---- lane-parallel metadata: lanes 0..7 fetch (deg,start) ----
    int myDeg = 0, myStart = 0;
    {
        int nd = n0 + warp * 8 + lane;
        if (lane < 8 && nd < N) {
            myDeg   = g_cnt[nd];
            myStart = g_rowptr[nd];
        }
    }

    // ---- aggregate: one node per HALF-WARP (2 concurrent per warp),
    //      4 independent accumulators -> 4 loads in flight per half-warp.
    //      All shuffles inside the (deg-divergent) region use hmask/width16.
    for (int t = 0; t < 4; t++) {
        int nl    = t * 2 + half;            // 0..7 within warp
        int nloc  = warp * 8 + nl;
        int node  = n0 + nloc;
        // warp-uniform point: full-mask broadcast is safe here
        int deg   = __shfl_sync(0xffffffffu, myDeg, nl);
        int start = __shfl_sync(0xffffffffu, myStart, nl);
        float4 a0 = make_float4(0.f, 0.f, 0.f, 0.f);
        float4 a1 = a0, a2 = a0, a3 = a0;
        float inv = 1.f;
        if (node < N) {
            start = min(start, E_MAX - deg);          // defensive: no OOB reads
            start = max(start, 0);
            for (int base = 0; base < deg; base += 16) {
                int rem = deg - base;
                int cnt = rem < 16 ? rem : 16;
                int myidx = (sub < cnt) ? g_ebuf[start + base + sub] : 0;
                for (int j = 0; j < cnt; j += 4) {
                    int s0 = __shfl_sync(hmask, myidx, j + 0, 16);
                    int s1 = __shfl_sync(hmask, myidx, j + 1, 16);
                    int s2 = __shfl_sync(hmask, myidx, j + 2, 16);
                    int s3 = __shfl_sync(hmask, myidx, j + 3, 16);
                    if (j + 0 < cnt) {
                        float4 v = __ldg(x4 + (size_t)s0 * 16 + sub);
                        a0.x += v.x; a0.y += v.y; a0.z += v.z; a0.w += v.w;
                    }
                    if (j + 1 < cnt) {
                        float4 v = __ldg(x4 + (size_t)s1 * 16 + sub);
                        a1.x += v.x; a1.y += v.y; a1.z += v.z; a1.w += v.w;
                    }
                    if (j + 2 < cnt) {
                        float4 v = __ldg(x4 + (size_t)s2 * 16 + sub);
                        a2.x += v.x; a2.y += v.y; a2.z += v.z; a2.w += v.w;
                    }
                    if (j + 3 < cnt) {
                        float4 v = __ldg(x4 + (size_t)s3 * 16 + sub);
                        a3.x += v.x; a3.y += v.y; a3.z += v.z; a3.w += v.w;
                    }
                }
            }
            a0.x += a1.x; a0.y += a1.y; a0.z += a1.z; a0.w += a1.w;
            a2.x += a3.x; a2.y += a3.y; a2.z += a3.z; a2.w += a3.w;
            a0.x += a2.x; a0.y += a2.y; a0.z += a2.z; a0.w += a2.w;
            inv = 1.0f / (float)(deg > 1 ? deg : 1);
        }
        // half-warp owns the full row: contiguous float4 -> conflict-free
        float4 st = make_float4(a0.x * inv, a0.y * inv, a0.z * inv, a0.w * inv);
        *(float4*)&As[nloc][4 * sub] = st;
    }
    __syncthreads();

    // ---- MMA kt=0 (agg half) ----
    mma_tile(As, Ws, acc, tx, ty);
    __syncthreads();

    // ---- stage Ws (kt=1) + x tile (row-major, 2 nodes in flight) ----
    stage_ws(Ws, 1, tid);
    for (int t = half; t < 8; t += 2) {
        int nloc = warp * 8 + t;
        int node = n0 + nloc;
        float4 v = make_float4(0.f, 0.f, 0.f, 0.f);
        if (node < N) v = __ldg(x4 + (size_t)node * 16 + sub);
        *(float4*)&As[nloc][4 * sub] = v;
    }
    __syncthreads();

    // ---- MMA kt=1 (self half) ----
    mma_tile(As, Ws, acc, tx, ty);

    // ---- epilogue: +bias, float4 stores (thread owns 4 full node rows) ----
    float4 bv = *(const float4*)(bias + tx * 4);
    #pragma unroll
    for (int i = 0; i < 4; i++) {
        int n = n0 + ty * 4 + i;
        if (n < N) {
            float2 lo = unpack2(acc[i][0]);
            float2 hi = unpack2(acc[i][1]);
            float4 o4 = make_float4(lo.x + bv.x, lo.y + bv.y, hi.x + bv.z, hi.y + bv.w);
            ((float4*)out)[(size_t)n * 16 + tx] = o4;
        }
    }

    // ---- zero own g_cnt slice for the next call ----
    if (tid < 64) {
        int n = n0 + tid;
        if (n < N) g_cnt[n] = 0;
    }
}

// --------------------------------------------------------------------------
extern "C" void kernel_launch(void* const* d_in, const int* in_sizes, int n_in,
                              void* d_out, int out_size) {
    const float* x  = nullptr;
    const int*   ei = nullptr;
    const float* W  = nullptr;
    const float* b  = nullptr;
    int xsz = 0, esz = 0;

    for (int i = 0; i < n_in; i++) {
        int sz = in_sizes[i];
        if (sz == 64) b = (const float*)d_in[i];
        else if (sz == 8192) W = (const float*)d_in[i];
        else if (sz <= 2) { /* num_nodes scalar */ }
        else {
            if (sz > xsz) {
                if (x) { ei = (const int*)x; esz = xsz; }
                x = (const float*)d_in[i]; xsz = sz;
            } else { ei = (const int*)d_in[i]; esz = sz; }
        }
    }
    if (!x  && n_in > 0) { x  = (const float*)d_in[0]; xsz = in_sizes[0]; }
    if (!ei && n_in > 1) { ei = (const int*)d_in[1];   esz = in_sizes[1]; }
    if (!W  && n_in > 3) W = (const float*)d_in[n_in - 2];
    if (!b  && n_in > 4) b = (const float*)d_in[n_in - 1];

    float* out = (float*)d_out;
    int N = xsz / F;
    int E = esz / 2;
    if (N > N_MAX) N = N_MAX;
    if (E > E_MAX) E = E_MAX;

    int et = (E + 3) / 4;   // 4 edges per thread
    hist_kernel<<<(et + 255) / 256, 256>>>(ei, E, N);
    alloc_kernel<<<(N + 255) / 256, 256>>>(N, W);
    fill_kernel<<<(et + 255) / 256, 256>>>(ei, E, N);
    fused_kernel<<<(N + 63) / 64, 256>>>((const float4*)x, b, out, N);
}